// round 11
// baseline (speedup 1.0000x reference)
#include <cuda_runtime.h>

#define B_  4
#define S_  2048
#define DM_ 1024
#define H_  16
#define DK_ 64
#define M_  (B_*S_)   // 8192 rows

// Scratch (allocation-free rule: __device__ globals)
__device__ float g_Qh[(size_t)B_*H_*S_*DK_];
__device__ float g_Kh[(size_t)B_*H_*S_*DK_];
__device__ float g_Vh[(size_t)B_*H_*S_*DK_];
__device__ float g_Ctx[(size_t)M_*DM_];
__device__ float g_invl[(size_t)B_*H_*S_];
__device__ unsigned g_mbits[(size_t)B_*S_*(S_/32)];   // packed mask bits

// ---------------------------------------------------------------------------
// helpers
// ---------------------------------------------------------------------------
__device__ __forceinline__ unsigned f2tf(float x) {
    unsigned u;
    asm("cvt.rna.tf32.f32 %0, %1;" : "=r"(u) : "f"(x));
    return u;
}
__device__ __forceinline__ void mma_tf32(float c[4],
                                         unsigned a0, unsigned a1, unsigned a2, unsigned a3,
                                         unsigned b0, unsigned b1) {
    asm("mma.sync.aligned.m16n8k8.row.col.f32.tf32.tf32.f32 "
        "{%0,%1,%2,%3},{%4,%5,%6,%7},{%8,%9},{%0,%1,%2,%3};"
        : "+f"(c[0]), "+f"(c[1]), "+f"(c[2]), "+f"(c[3])
        : "r"(a0), "r"(a1), "r"(a2), "r"(a3), "r"(b0), "r"(b1));
}
__device__ __forceinline__ unsigned sm_u32(const void* p) {
    return (unsigned)__cvta_generic_to_shared(p);
}
__device__ __forceinline__ void ldsm4(unsigned r[4], unsigned addr) {
    asm volatile("ldmatrix.sync.aligned.m8n8.x4.shared.b16 {%0,%1,%2,%3}, [%4];"
        : "=r"(r[0]), "=r"(r[1]), "=r"(r[2]), "=r"(r[3]) : "r"(addr));
}
__device__ __forceinline__ void cp16(unsigned dst, const void* src) {
    asm volatile("cp.async.cg.shared.global [%0], [%1], 16;" :: "r"(dst), "l"(src));
}
__device__ __forceinline__ void cp_commit() {
    asm volatile("cp.async.commit_group;");
}
__device__ __forceinline__ void cp_wait0() {
    asm volatile("cp.async.wait_group 0;" ::: "memory");
}

// ---------------------------------------------------------------------------
// Fused projection GEMM (up to 3 independent GEMMs per launch, selected by
// bid>>9) + aux memory work in blocks >= nProj.
// Proj: 128x128 tile, BK=32, 8 warps 2(m)x4(n), warp 64m x 32n (2 CTAs/SM).
//   auxMode 1: pack mask bits (block packs 256 words; 2048*256 = all words)
//   auxMode 2: rescale 64 attention rows by g_invl (2048*64 = all rows)
// ---------------------------------------------------------------------------
#define XSTR 36
__global__ __launch_bounds__(256) void proj_fused(const float* __restrict__ X0,
                                                  const float* __restrict__ W0,
                                                  float* __restrict__ Y0,
                                                  const float* __restrict__ X1,
                                                  const float* __restrict__ W1,
                                                  float* __restrict__ Y1,
                                                  const float* __restrict__ X2,
                                                  const float* __restrict__ W2,
                                                  float* __restrict__ Y2,
                                                  const float* __restrict__ bias,
                                                  int headsMode, int auxMode,
                                                  int nProj,
                                                  const int* __restrict__ mask,
                                                  float* __restrict__ attnRS)
{
    const int bid = blockIdx.x;
    if (bid >= nProj) {
        const int aux = bid - nProj;
        if (auxMode == 1) {            // ---- pack mask bits ----
            const int lane = threadIdx.x & 31, w = threadIdx.x >> 5;
            size_t base = (size_t)aux * 256 + (size_t)w * 32;
            #pragma unroll 4
            for (int i = 0; i < 32; i++) {
                int m = mask[(base + i) * 32 + lane];
                unsigned bits = __ballot_sync(0xffffffffu, m != 0);
                if (lane == 0) g_mbits[base + i] = bits;
            }
        } else {                       // ---- rescale 64 attention rows ----
            const int t = threadIdx.x;
            #pragma unroll 4
            for (int r = 0; r < 64; r++) {
                const int row = aux * 64 + r;
                const float s = g_invl[row];
                float4* p = (float4*)(attnRS + (size_t)row * S_);
                float4 v0 = p[t], v1 = p[t + 256];
                v0.x *= s; v0.y *= s; v0.z *= s; v0.w *= s;
                v1.x *= s; v1.y *= s; v1.z *= s; v1.w *= s;
                p[t] = v0; p[t + 256] = v1;
            }
        }
        return;
    }

    const int which = bid >> 9;        // which GEMM (0..2)
    const int sub = bid & 511;
    const float* X = (which == 0) ? X0 : (which == 1) ? X1 : X2;
    const float* W = (which == 0) ? W0 : (which == 1) ? W1 : W2;
    float*       Y = (which == 0) ? Y0 : (which == 1) ? Y1 : Y2;

    __shared__ unsigned Xs[128 * XSTR];
    __shared__ unsigned Ws[128 * XSTR];
    const int tid = threadIdx.x;
    const int lane = tid & 31, wid = tid >> 5;
    const int wm = wid >> 2, wn = wid & 3;
    const int gr = lane >> 2, tg = lane & 3;
    const int m0 = (sub & 63) * 128, n0 = (sub >> 6) * 128;

    const int arow = lane & 15;
    const int acol = ((lane >> 4) & 1) * 4;
    const int brow = ((lane >> 4) & 1) * 8 + (lane & 7);
    const int bcol = ((lane >> 3) & 1) * 4;
    const unsigned abase = sm_u32(Xs + (wm*64 + arow)*XSTR + acol);
    const unsigned bbase = sm_u32(Ws + (wn*32 + brow)*XSTR + bcol);

    const int lr = tid >> 1;          // 0..127 (row)
    const int lh = (tid & 1) * 16;    // k-half

    float c[4][4][4];
    #pragma unroll
    for (int mi = 0; mi < 4; mi++)
        #pragma unroll
        for (int ni = 0; ni < 4; ni++)
            #pragma unroll
            for (int r = 0; r < 4; r++) c[mi][ni][r] = 0.f;

    const float* Xp = X + (size_t)(m0 + lr) * DM_ + lh;
    const float* Wp = W + (size_t)(n0 + lr) * DM_ + lh;

    float4 px[4], pw[4];
    #pragma unroll
    for (int j = 0; j < 4; j++) { px[j] = *(const float4*)(Xp + 4*j); pw[j] = *(const float4*)(Wp + 4*j); }

    #pragma unroll 1
    for (int it = 0; it < 32; it++) {
        #pragma unroll
        for (int j = 0; j < 4; j++) {
            *(uint4*)&Xs[lr*XSTR + lh + 4*j] = make_uint4(f2tf(px[j].x), f2tf(px[j].y), f2tf(px[j].z), f2tf(px[j].w));
            *(uint4*)&Ws[lr*XSTR + lh + 4*j] = make_uint4(f2tf(pw[j].x), f2tf(pw[j].y), f2tf(pw[j].z), f2tf(pw[j].w));
        }
        __syncthreads();

        if (it + 1 < 32) {
            const int ko = (it + 1) * 32;
            #pragma unroll
            for (int j = 0; j < 4; j++) { px[j] = *(const float4*)(Xp + ko + 4*j); pw[j] = *(const float4*)(Wp + ko + 4*j); }
        }

        #pragma unroll
        for (int kc = 0; kc < 4; kc++) {
            unsigned a[4][4], bb[4][2];
            #pragma unroll
            for (int mi = 0; mi < 4; mi++)
                ldsm4(a[mi], abase + (unsigned)(mi*16*XSTR + kc*8) * 4u);
            #pragma unroll
            for (int np = 0; np < 2; np++) {
                unsigned t[4];
                ldsm4(t, bbase + (unsigned)(np*16*XSTR + kc*8) * 4u);
                bb[2*np][0] = t[0]; bb[2*np][1] = t[1];
                bb[2*np+1][0] = t[2]; bb[2*np+1][1] = t[3];
            }
            #pragma unroll
            for (int mi = 0; mi < 4; mi++)
                #pragma unroll
                for (int ni = 0; ni < 4; ni++)
                    mma_tf32(c[mi][ni], a[mi][0], a[mi][1], a[mi][2], a[mi][3],
                             bb[ni][0], bb[ni][1]);
        }
        __syncthreads();
    }

    if (headsMode) {
        #pragma unroll
        for (int mi = 0; mi < 4; mi++) {
            int m = m0 + wm*64 + mi*16 + gr;
            int b = m >> 11, s = m & (S_ - 1);
            #pragma unroll
            for (int ni = 0; ni < 4; ni++) {
                int n = n0 + wn*32 + ni*8 + 2*tg;
                int h = n >> 6, dk = n & 63;
                size_t base = (((size_t)(b*H_ + h) * S_) + s) * DK_ + dk;
                *(float2*)&Y[base]         = make_float2(c[mi][ni][0], c[mi][ni][1]);
                *(float2*)&Y[base + 8*DK_] = make_float2(c[mi][ni][2], c[mi][ni][3]);
            }
        }
    } else {
        #pragma unroll
        for (int mi = 0; mi < 4; mi++) {
            int m = m0 + wm*64 + mi*16 + gr;
            #pragma unroll
            for (int ni = 0; ni < 4; ni++) {
                int n = n0 + wn*32 + ni*8 + 2*tg;
                float b0 = bias[n], b1 = bias[n+1];
                *(float2*)&Y[(size_t)m * DM_ + n] =
                    make_float2(c[mi][ni][0] + b0, c[mi][ni][1] + b1);
                *(float2*)&Y[(size_t)(m+8) * DM_ + n] =
                    make_float2(c[mi][ni][2] + b0, c[mi][ni][3] + b1);
            }
        }
    }
}

// ---------------------------------------------------------------------------
// Fused attention, 512 threads / 16 warps, software-pipelined cp.async:
// K double-buffered (issued one tile ahead), V issued at tile top, single
// wait_group 0 deferred to after scores+exp. 2 syncthreads per tile.
// Scores: warps 4x4, warp 32q x 32k (tf32). PV: warps 4x4, warp 32q x 16d.
// smem words: Qs 8704 | Ks0 8704 | Ks1 8704 | Vs 9216 | Ps 16896 | rowSum 128
// ---------------------------------------------------------------------------
#define QSTR 68
#define VSTR 72
#define PSTR2 132
#define OFF_KS0 8704
#define OFF_KS1 17408
#define OFF_VS  26112
#define OFF_PS  35328
#define OFF_RS  52224
#define SM_WORDS 52352
#define KBYTES (8704u * 4u)

__global__ __launch_bounds__(512) void attn_mma(float* __restrict__ attn)
{
    extern __shared__ unsigned smu[];
    unsigned* Qs = smu;
    unsigned* Ks = smu + OFF_KS0;  // two buffers of 8704 words
    unsigned* Vs = smu + OFF_VS;   // natural [key][d], stride 72
    unsigned* Ps = smu + OFF_PS;
    float* rowSum = (float*)(smu + OFF_RS);

    const int tid = threadIdx.x;
    const int lane = tid & 31, wid = tid >> 5;
    const int wm = wid >> 2, wn = wid & 3;       // score map: 32q x 32k
    const int wm2 = wid & 3, wn2 = wid >> 2;     // PV map:    32q x 16d
    const int gr = lane >> 2, tg = lane & 3;
    const int qt = blockIdx.x, bh = blockIdx.y;
    const int b = bh >> 4, h = bh & 15;

    const int arow = lane & 15;
    const int acol = ((lane >> 4) & 1) * 4;
    const int brow = ((lane >> 4) & 1) * 8 + (lane & 7);
    const int bcol = ((lane >> 3) & 1) * 4;
    const unsigned qbase = sm_u32(Qs + (wm*32 + arow)*QSTR + acol);
    const unsigned kbase = sm_u32(Ks + (wn*32 + brow)*QSTR + bcol);
    const unsigned pbase = sm_u32(Ps + (wm2*32 + arow)*PSTR2 + acol);

    const float* Qb = g_Qh + ((size_t)bh * S_ + qt*128) * DK_;
    const float* Kb = g_Kh + (size_t)bh * S_ * DK_;
    const float* Vb = g_Vh + (size_t)bh * S_ * DK_;
    const unsigned* mbp = g_mbits + ((size_t)b * S_ + qt*128) * (S_/32);
    float* ab = attn + (size_t)bh * S_ * S_ + (size_t)qt * 128 * S_;

    if (tid < 128) rowSum[tid] = 0.f;

    const int lr = tid >> 2;            // 0..127
    const int seg = (tid & 3) * 16;     // d quarter
    const unsigned ksts = sm_u32(Ks + lr*QSTR + seg);
    const unsigned vsts = sm_u32(Vs + lr*VSTR + seg);

    { // Q load: scale by 1/sqrt(64), tf32 round (RNA)
        const float* qp = Qb + (size_t)lr * DK_ + seg;
        #pragma unroll
        for (int j = 0; j < 4; j++) {
            float4 v = *(const float4*)(qp + 4*j);
            *(uint4*)&Qs[lr*QSTR + seg + 4*j] =
                make_uint4(f2tf(v.x*0.125f), f2tf(v.y*0.125f),
                           f2tf(v.z*0.125f), f2tf(v.w*0.125f));
        }
    }
    { // prologue: K[0] into buffer 0
        const float* kp = Kb + (size_t)lr * DK_ + seg;
        #pragma unroll
        for (int j = 0; j < 4; j++) cp16(ksts + 16u*j, kp + 4*j);
        cp_commit();
        cp_wait0();
    }

    float lacc[4];
    #pragma unroll
    for (int i = 0; i < 4; i++) lacc[i] = 0.f;
    float cacc[2][2][4];
    #pragma unroll
    for (int mi = 0; mi < 2; mi++)
        #pragma unroll
        for (int f = 0; f < 2; f++)
            #pragma unroll
            for (int r = 0; r < 4; r++) cacc[mi][f][r] = 0.f;

    for (int kt = 0; kt < 16; kt++) {
        __syncthreads();   // prev PV done with Vs/Ps; K[kt] visible (prev-iter wait + sync)
        { // issue V[kt]; prefetch K[kt+1] into alternate buffer
            const float* vp = Vb + (size_t)(kt*128 + lr) * DK_ + seg;
            #pragma unroll
            for (int j = 0; j < 4; j++) cp16(vsts + 16u*j, vp + 4*j);
            if (kt + 1 < 16) {
                const float* kp = Kb + (size_t)((kt+1)*128 + lr) * DK_ + seg;
                const unsigned kdst = ksts + ((kt+1) & 1) * KBYTES;
                #pragma unroll
                for (int j = 0; j < 4; j++) cp16(kdst + 16u*j, kp + 4*j);
            }
            cp_commit();
        }
        // mask word prefetch (bits for this warp's 32-key window)
        unsigned mw[2][2];
        #pragma unroll
        for (int mi = 0; mi < 2; mi++) {
            const int r0 = wm*32 + mi*16 + gr;
            mw[mi][0] = mbp[(size_t)r0      * (S_/32) + kt*4 + wn];
            mw[mi][1] = mbp[(size_t)(r0+8)  * (S_/32) + kt*4 + wn];
        }

        // ---- scores on K[kt] (buffer kt&1): warp 32q x 32k, k-dim 64 ----
        const unsigned kb = kbase + (kt & 1) * KBYTES;
        float sc[2][4][4];
        #pragma unroll
        for (int mi = 0; mi < 2; mi++)
            #pragma unroll
            for (int ni = 0; ni < 4; ni++)
                #pragma unroll
                for (int r = 0; r < 4; r++) sc[mi][ni][r] = 0.f;

        #pragma unroll
        for (int kc = 0; kc < 8; kc++) {
            unsigned a[2][4], bb[4][2];
            #pragma unroll
            for (int mi = 0; mi < 2; mi++)
                ldsm4(a[mi], qbase + (unsigned)(mi*16*QSTR + kc*8) * 4u);
            #pragma unroll
            for (int np = 0; np < 2; np++) {
                unsigned t[4];
                ldsm4(t, kb + (unsigned)(np*16*QSTR + kc*8) * 4u);
                bb[2*np][0] = t[0]; bb[2*np][1] = t[1];
                bb[2*np+1][0] = t[2]; bb[2*np+1][1] = t[3];
            }
            #pragma unroll
            for (int mi = 0; mi < 2; mi++)
                #pragma unroll
                for (int ni = 0; ni < 4; ni++)
                    mma_tf32(sc[mi][ni], a[mi][0], a[mi][1], a[mi][2], a[mi][3],
                             bb[ni][0], bb[ni][1]);
        }

        // ---- mask(bits) + exp; unnormalized probs -> global(fp32) + Ps(tf32) ----
        #pragma unroll
        for (int mi = 0; mi < 2; mi++) {
            const int r0 = wm*32 + mi*16 + gr;
            #pragma unroll
            for (int ni = 0; ni < 4; ni++) {
                const int ck = wn*32 + ni*8 + 2*tg;
                const int bit = ni*8 + 2*tg;
                const size_t gcol = (size_t)kt*128 + ck;
                float p00 = (mw[mi][0] >> bit     & 1u) ? __expf(sc[mi][ni][0]) : 0.f;
                float p01 = (mw[mi][0] >> (bit+1) & 1u) ? __expf(sc[mi][ni][1]) : 0.f;
                float p10 = (mw[mi][1] >> bit     & 1u) ? __expf(sc[mi][ni][2]) : 0.f;
                float p11 = (mw[mi][1] >> (bit+1) & 1u) ? __expf(sc[mi][ni][3]) : 0.f;
                lacc[mi*2]   += p00 + p01;
                lacc[mi*2+1] += p10 + p11;
                *(float2*)&ab[(size_t)r0     * S_ + gcol] = make_float2(p00, p01);
                *(float2*)&ab[(size_t)(r0+8) * S_ + gcol] = make_float2(p10, p11);
                *(uint2*)&Ps[r0    *PSTR2 + ck] = make_uint2(f2tf(p00), f2tf(p01));
                *(uint2*)&Ps[(r0+8)*PSTR2 + ck] = make_uint2(f2tf(p10), f2tf(p11));
            }
        }
        cp_wait0();        // V[kt] (and K[kt+1]) landed — overlapped with scores+exp
        __syncthreads();   // P + V visible to all threads

        // ---- PV: warp tile 32q x 16d, k-dim = 128 keys ----
        #pragma unroll
        for (int kc = 0; kc < 16; kc++) {
            unsigned a2[2][4];
            ldsm4(a2[0], pbase + (unsigned)(kc*8) * 4u);
            ldsm4(a2[1], pbase + (unsigned)(16*PSTR2 + kc*8) * 4u);
            unsigned vb[2][2];
            #pragma unroll
            for (int f = 0; f < 2; f++) {
                const int d = wn2*16 + f*8 + gr;
                vb[f][0] = Vs[(kc*8 + tg    )*VSTR + d];
                vb[f][1] = Vs[(kc*8 + tg + 4)*VSTR + d];
            }
            #pragma unroll
            for (int mi = 0; mi < 2; mi++)
                #pragma unroll
                for (int f = 0; f < 2; f++)
                    mma_tf32(cacc[mi][f], a2[mi][0], a2[mi][1], a2[mi][2], a2[mi][3],
                             vb[f][0], vb[f][1]);
        }
    }

    // ---- row sums: quad shuffle reduce + cross-warp atomic ----
    #pragma unroll
    for (int i = 0; i < 4; i++) {
        float v = lacc[i];
        v += __shfl_xor_sync(0xffffffffu, v, 1);
        v += __shfl_xor_sync(0xffffffffu, v, 2);
        lacc[i] = v;
    }
    if (tg == 0) {
        #pragma unroll
        for (int mi = 0; mi < 2; mi++) {
            atomicAdd(&rowSum[wm*32 + mi*16 + gr],     lacc[mi*2]);
            atomicAdd(&rowSum[wm*32 + mi*16 + gr + 8], lacc[mi*2+1]);
        }
    }
    __syncthreads();
    if (tid < 128)
        g_invl[(size_t)bh * S_ + qt*128 + tid] = 1.0f / rowSum[tid];

    // ---- context write (scaled by 1/l), permuted to [b][s][h*64+d] ----
    #pragma unroll
    for (int mi = 0; mi < 2; mi++) {
        const int r0 = wm2*32 + mi*16 + gr;
        const float s0 = 1.0f / rowSum[r0];
        const float s1 = 1.0f / rowSum[r0 + 8];
        #pragma unroll
        for (int f = 0; f < 2; f++) {
            const int d = wn2*16 + f*8 + 2*tg;
            size_t d0 = ((size_t)(b*S_ + qt*128 + r0    )) * DM_ + h*DK_ + d;
            size_t d1 = ((size_t)(b*S_ + qt*128 + r0 + 8)) * DM_ + h*DK_ + d;
            *(float2*)&g_Ctx[d0] = make_float2(cacc[mi][f][0]*s0, cacc[mi][f][1]*s0);
            *(float2*)&g_Ctx[d1] = make_float2(cacc[mi][f][2]*s1, cacc[mi][f][3]*s1);
        }
    }
}

// ---------------------------------------------------------------------------
extern "C" void kernel_launch(void* const* d_in, const int* in_sizes, int n_in,
                              void* d_out, int out_size)
{
    const float* q    = (const float*)d_in[0];
    const float* k    = (const float*)d_in[1];
    const float* v    = (const float*)d_in[2];
    const int*   mask = (const int*)  d_in[3];
    const float* Wq   = (const float*)d_in[4];
    const float* Wk   = (const float*)d_in[5];
    const float* Wv   = (const float*)d_in[6];
    const float* Wo   = (const float*)d_in[7];
    const float* bo   = (const float*)d_in[8];

    float* out      = (float*)d_out;
    float* ctx_out  = out;                             // [B,S,DM]
    float* attn_out = out + (size_t)B_ * S_ * DM_;     // [B,H,S,S]

    void *pQ, *pK, *pV, *pC;
    cudaGetSymbolAddress(&pQ, g_Qh);
    cudaGetSymbolAddress(&pK, g_Kh);
    cudaGetSymbolAddress(&pV, g_Vh);
    cudaGetSymbolAddress(&pC, g_Ctx);

    const int smemAttn = SM_WORDS * 4;   // 209408
    cudaFuncSetAttribute(attn_mma, cudaFuncAttributeMaxDynamicSharedMemorySize, smemAttn);

    // All three QKV projections in ONE launch (1536 proj blocks, 3 GEMMs by
    // bid>>9) + 2048 mask-pack aux blocks filling the wave tail.
    proj_fused<<<1536 + 2048, 256>>>(q, Wq, (float*)pQ,
                                     k, Wk, (float*)pK,
                                     v, Wv, (float*)pV,
                                     nullptr, 1, 1, 1536, mask, nullptr);

    attn_mma<<<dim3(S_/128, B_*H_), 512, smemAttn>>>(attn_out);

    // Output projection (512 blocks) + attention rescale (2048 aux blocks)
    proj_fused<<<512 + 2048, 256>>>((const float*)pC, Wo, ctx_out,
                                    nullptr, nullptr, nullptr,
                                    nullptr, nullptr, nullptr,
                                    bo, 0, 2, 512, nullptr, attn_out);
}

// round 12
// speedup vs baseline: 1.2157x; 1.2157x over previous
#include <cuda_runtime.h>

#define B_  4
#define S_  2048
#define DM_ 1024
#define H_  16
#define DK_ 64
#define M_  (B_*S_)   // 8192 rows

// Scratch (allocation-free rule: __device__ globals)
__device__ float g_Qh[(size_t)B_*H_*S_*DK_];
__device__ float g_Kh[(size_t)B_*H_*S_*DK_];
__device__ float g_Vh[(size_t)B_*H_*S_*DK_];
__device__ float g_Ctx[(size_t)M_*DM_];
__device__ float g_invl[(size_t)B_*H_*S_];
__device__ unsigned g_mbits[(size_t)B_*S_*(S_/32)];   // packed mask bits

// ---------------------------------------------------------------------------
// helpers
// ---------------------------------------------------------------------------
__device__ __forceinline__ unsigned f2tf(float x) {
    unsigned u;
    asm("cvt.rna.tf32.f32 %0, %1;" : "=r"(u) : "f"(x));
    return u;
}
__device__ __forceinline__ void mma_tf32(float c[4],
                                         unsigned a0, unsigned a1, unsigned a2, unsigned a3,
                                         unsigned b0, unsigned b1) {
    asm("mma.sync.aligned.m16n8k8.row.col.f32.tf32.tf32.f32 "
        "{%0,%1,%2,%3},{%4,%5,%6,%7},{%8,%9},{%0,%1,%2,%3};"
        : "+f"(c[0]), "+f"(c[1]), "+f"(c[2]), "+f"(c[3])
        : "r"(a0), "r"(a1), "r"(a2), "r"(a3), "r"(b0), "r"(b1));
}
__device__ __forceinline__ unsigned sm_u32(const void* p) {
    return (unsigned)__cvta_generic_to_shared(p);
}
__device__ __forceinline__ void ldsm4(unsigned r[4], unsigned addr) {
    asm volatile("ldmatrix.sync.aligned.m8n8.x4.shared.b16 {%0,%1,%2,%3}, [%4];"
        : "=r"(r[0]), "=r"(r[1]), "=r"(r[2]), "=r"(r[3]) : "r"(addr));
}
__device__ __forceinline__ void cp16(unsigned dst, const void* src) {
    asm volatile("cp.async.cg.shared.global [%0], [%1], 16;" :: "r"(dst), "l"(src));
}
__device__ __forceinline__ void cp_commit() {
    asm volatile("cp.async.commit_group;");
}
__device__ __forceinline__ void cp_wait0() {
    asm volatile("cp.async.wait_group 0;" ::: "memory");
}

// ---------------------------------------------------------------------------
// Fused projection GEMM (up to 3 independent GEMMs per launch, selected by
// bid>>9) + aux memory work in blocks >= nProj.
// Proj: 128x128 tile, BK=32, 8 warps 2(m)x4(n), warp 64m x 32n.
// __launch_bounds__(256, 2) pins regs <= 128 so 2 CTAs/SM co-reside — the
// R11 regression was regs creeping to 130 (1 CTA/SM).
//   auxMode 1: pack mask bits (block packs 256 words; 2048*256 = all words)
//   auxMode 2: rescale 64 attention rows by g_invl (2048*64 = all rows)
// ---------------------------------------------------------------------------
#define XSTR 36
__global__ __launch_bounds__(256, 2) void proj_fused(
    const float* __restrict__ X0, const float* __restrict__ W0, float* __restrict__ Y0,
    const float* __restrict__ X1, const float* __restrict__ W1, float* __restrict__ Y1,
    const float* __restrict__ X2, const float* __restrict__ W2, float* __restrict__ Y2,
    const float* __restrict__ bias,
    int headsMode, int auxMode, int nProj,
    const int* __restrict__ mask,
    float* __restrict__ attnRS)
{
    const int bid = blockIdx.x;
    if (bid >= nProj) {
        const int aux = bid - nProj;
        if (auxMode == 1) {            // ---- pack mask bits ----
            const int lane = threadIdx.x & 31, w = threadIdx.x >> 5;
            size_t base = (size_t)aux * 256 + (size_t)w * 32;
            #pragma unroll 4
            for (int i = 0; i < 32; i++) {
                int m = mask[(base + i) * 32 + lane];
                unsigned bits = __ballot_sync(0xffffffffu, m != 0);
                if (lane == 0) g_mbits[base + i] = bits;
            }
        } else {                       // ---- rescale 64 attention rows ----
            const int t = threadIdx.x;
            #pragma unroll 4
            for (int r = 0; r < 64; r++) {
                const int row = aux * 64 + r;
                const float s = g_invl[row];
                float4* p = (float4*)(attnRS + (size_t)row * S_);
                float4 v0 = p[t], v1 = p[t + 256];
                v0.x *= s; v0.y *= s; v0.z *= s; v0.w *= s;
                v1.x *= s; v1.y *= s; v1.z *= s; v1.w *= s;
                p[t] = v0; p[t + 256] = v1;
            }
        }
        return;
    }

    const int which = bid >> 9;        // which GEMM (0..2)
    const int sub = bid & 511;
    const float* X = (which == 0) ? X0 : (which == 1) ? X1 : X2;
    const float* W = (which == 0) ? W0 : (which == 1) ? W1 : W2;
    float*       Y = (which == 0) ? Y0 : (which == 1) ? Y1 : Y2;

    __shared__ unsigned Xs[128 * XSTR];
    __shared__ unsigned Ws[128 * XSTR];
    const int tid = threadIdx.x;
    const int lane = tid & 31, wid = tid >> 5;
    const int wm = wid >> 2, wn = wid & 3;
    const int gr = lane >> 2, tg = lane & 3;
    const int m0 = (sub & 63) * 128, n0 = (sub >> 6) * 128;

    const int arow = lane & 15;
    const int acol = ((lane >> 4) & 1) * 4;
    const int brow = ((lane >> 4) & 1) * 8 + (lane & 7);
    const int bcol = ((lane >> 3) & 1) * 4;
    const unsigned abase = sm_u32(Xs + (wm*64 + arow)*XSTR + acol);
    const unsigned bbase = sm_u32(Ws + (wn*32 + brow)*XSTR + bcol);

    const int lr = tid >> 1;          // 0..127 (row)
    const int lh = (tid & 1) * 16;    // k-half

    float c[4][4][4];
    #pragma unroll
    for (int mi = 0; mi < 4; mi++)
        #pragma unroll
        for (int ni = 0; ni < 4; ni++)
            #pragma unroll
            for (int r = 0; r < 4; r++) c[mi][ni][r] = 0.f;

    const float* Xp = X + (size_t)(m0 + lr) * DM_ + lh;
    const float* Wp = W + (size_t)(n0 + lr) * DM_ + lh;

    float4 px[4], pw[4];
    #pragma unroll
    for (int j = 0; j < 4; j++) { px[j] = *(const float4*)(Xp + 4*j); pw[j] = *(const float4*)(Wp + 4*j); }

    #pragma unroll 1
    for (int it = 0; it < 32; it++) {
        #pragma unroll
        for (int j = 0; j < 4; j++) {
            *(uint4*)&Xs[lr*XSTR + lh + 4*j] = make_uint4(f2tf(px[j].x), f2tf(px[j].y), f2tf(px[j].z), f2tf(px[j].w));
            *(uint4*)&Ws[lr*XSTR + lh + 4*j] = make_uint4(f2tf(pw[j].x), f2tf(pw[j].y), f2tf(pw[j].z), f2tf(pw[j].w));
        }
        __syncthreads();

        if (it + 1 < 32) {
            const int ko = (it + 1) * 32;
            #pragma unroll
            for (int j = 0; j < 4; j++) { px[j] = *(const float4*)(Xp + ko + 4*j); pw[j] = *(const float4*)(Wp + ko + 4*j); }
        }

        #pragma unroll
        for (int kc = 0; kc < 4; kc++) {
            unsigned a[4][4], bb[4][2];
            #pragma unroll
            for (int mi = 0; mi < 4; mi++)
                ldsm4(a[mi], abase + (unsigned)(mi*16*XSTR + kc*8) * 4u);
            #pragma unroll
            for (int np = 0; np < 2; np++) {
                unsigned t[4];
                ldsm4(t, bbase + (unsigned)(np*16*XSTR + kc*8) * 4u);
                bb[2*np][0] = t[0]; bb[2*np][1] = t[1];
                bb[2*np+1][0] = t[2]; bb[2*np+1][1] = t[3];
            }
            #pragma unroll
            for (int mi = 0; mi < 4; mi++)
                #pragma unroll
                for (int ni = 0; ni < 4; ni++)
                    mma_tf32(c[mi][ni], a[mi][0], a[mi][1], a[mi][2], a[mi][3],
                             bb[ni][0], bb[ni][1]);
        }
        __syncthreads();
    }

    if (headsMode) {
        #pragma unroll
        for (int mi = 0; mi < 4; mi++) {
            int m = m0 + wm*64 + mi*16 + gr;
            int b = m >> 11, s = m & (S_ - 1);
            #pragma unroll
            for (int ni = 0; ni < 4; ni++) {
                int n = n0 + wn*32 + ni*8 + 2*tg;
                int h = n >> 6, dk = n & 63;
                size_t base = (((size_t)(b*H_ + h) * S_) + s) * DK_ + dk;
                *(float2*)&Y[base]         = make_float2(c[mi][ni][0], c[mi][ni][1]);
                *(float2*)&Y[base + 8*DK_] = make_float2(c[mi][ni][2], c[mi][ni][3]);
            }
        }
    } else {
        #pragma unroll
        for (int mi = 0; mi < 4; mi++) {
            int m = m0 + wm*64 + mi*16 + gr;
            #pragma unroll
            for (int ni = 0; ni < 4; ni++) {
                int n = n0 + wn*32 + ni*8 + 2*tg;
                float b0 = bias[n], b1 = bias[n+1];
                *(float2*)&Y[(size_t)m * DM_ + n] =
                    make_float2(c[mi][ni][0] + b0, c[mi][ni][1] + b1);
                *(float2*)&Y[(size_t)(m+8) * DM_ + n] =
                    make_float2(c[mi][ni][2] + b0, c[mi][ni][3] + b1);
            }
        }
    }
}

// ---------------------------------------------------------------------------
// Fused attention, 512 threads / 16 warps, software-pipelined cp.async:
// K double-buffered (issued one tile ahead), V issued at tile top, single
// wait_group 0 deferred to after scores+exp. 2 syncthreads per tile.
// Scores: warps 4x4, warp 32q x 32k (tf32). PV: warps 4x4, warp 32q x 16d.
// smem words: Qs 8704 | Ks0 8704 | Ks1 8704 | Vs 9216 | Ps 16896 | rowSum 128
// ---------------------------------------------------------------------------
#define QSTR 68
#define VSTR 72
#define PSTR2 132
#define OFF_KS0 8704
#define OFF_KS1 17408
#define OFF_VS  26112
#define OFF_PS  35328
#define OFF_RS  52224
#define SM_WORDS 52352
#define KBYTES (8704u * 4u)

__global__ __launch_bounds__(512) void attn_mma(float* __restrict__ attn)
{
    extern __shared__ unsigned smu[];
    unsigned* Qs = smu;
    unsigned* Ks = smu + OFF_KS0;  // two buffers of 8704 words
    unsigned* Vs = smu + OFF_VS;   // natural [key][d], stride 72
    unsigned* Ps = smu + OFF_PS;
    float* rowSum = (float*)(smu + OFF_RS);

    const int tid = threadIdx.x;
    const int lane = tid & 31, wid = tid >> 5;
    const int wm = wid >> 2, wn = wid & 3;       // score map: 32q x 32k
    const int wm2 = wid & 3, wn2 = wid >> 2;     // PV map:    32q x 16d
    const int gr = lane >> 2, tg = lane & 3;
    const int qt = blockIdx.x, bh = blockIdx.y;
    const int b = bh >> 4, h = bh & 15;

    const int arow = lane & 15;
    const int acol = ((lane >> 4) & 1) * 4;
    const int brow = ((lane >> 4) & 1) * 8 + (lane & 7);
    const int bcol = ((lane >> 3) & 1) * 4;
    const unsigned qbase = sm_u32(Qs + (wm*32 + arow)*QSTR + acol);
    const unsigned kbase = sm_u32(Ks + (wn*32 + brow)*QSTR + bcol);
    const unsigned pbase = sm_u32(Ps + (wm2*32 + arow)*PSTR2 + acol);

    const float* Qb = g_Qh + ((size_t)bh * S_ + qt*128) * DK_;
    const float* Kb = g_Kh + (size_t)bh * S_ * DK_;
    const float* Vb = g_Vh + (size_t)bh * S_ * DK_;
    const unsigned* mbp = g_mbits + ((size_t)b * S_ + qt*128) * (S_/32);
    float* ab = attn + (size_t)bh * S_ * S_ + (size_t)qt * 128 * S_;

    if (tid < 128) rowSum[tid] = 0.f;

    const int lr = tid >> 2;            // 0..127
    const int seg = (tid & 3) * 16;     // d quarter
    const unsigned ksts = sm_u32(Ks + lr*QSTR + seg);
    const unsigned vsts = sm_u32(Vs + lr*VSTR + seg);

    { // Q load: scale by 1/sqrt(64), tf32 round (RNA)
        const float* qp = Qb + (size_t)lr * DK_ + seg;
        #pragma unroll
        for (int j = 0; j < 4; j++) {
            float4 v = *(const float4*)(qp + 4*j);
            *(uint4*)&Qs[lr*QSTR + seg + 4*j] =
                make_uint4(f2tf(v.x*0.125f), f2tf(v.y*0.125f),
                           f2tf(v.z*0.125f), f2tf(v.w*0.125f));
        }
    }
    { // prologue: K[0] into buffer 0
        const float* kp = Kb + (size_t)lr * DK_ + seg;
        #pragma unroll
        for (int j = 0; j < 4; j++) cp16(ksts + 16u*j, kp + 4*j);
        cp_commit();
        cp_wait0();
    }

    float lacc[4];
    #pragma unroll
    for (int i = 0; i < 4; i++) lacc[i] = 0.f;
    float cacc[2][2][4];
    #pragma unroll
    for (int mi = 0; mi < 2; mi++)
        #pragma unroll
        for (int f = 0; f < 2; f++)
            #pragma unroll
            for (int r = 0; r < 4; r++) cacc[mi][f][r] = 0.f;

    for (int kt = 0; kt < 16; kt++) {
        __syncthreads();   // prev PV done with Vs/Ps; K[kt] visible (prev-iter wait + sync)
        { // issue V[kt]; prefetch K[kt+1] into alternate buffer
            const float* vp = Vb + (size_t)(kt*128 + lr) * DK_ + seg;
            #pragma unroll
            for (int j = 0; j < 4; j++) cp16(vsts + 16u*j, vp + 4*j);
            if (kt + 1 < 16) {
                const float* kp = Kb + (size_t)((kt+1)*128 + lr) * DK_ + seg;
                const unsigned kdst = ksts + ((kt+1) & 1) * KBYTES;
                #pragma unroll
                for (int j = 0; j < 4; j++) cp16(kdst + 16u*j, kp + 4*j);
            }
            cp_commit();
        }
        // mask word prefetch (bits for this warp's 32-key window)
        unsigned mw[2][2];
        #pragma unroll
        for (int mi = 0; mi < 2; mi++) {
            const int r0 = wm*32 + mi*16 + gr;
            mw[mi][0] = mbp[(size_t)r0      * (S_/32) + kt*4 + wn];
            mw[mi][1] = mbp[(size_t)(r0+8)  * (S_/32) + kt*4 + wn];
        }

        // ---- scores on K[kt] (buffer kt&1): warp 32q x 32k, k-dim 64 ----
        const unsigned kb = kbase + (kt & 1) * KBYTES;
        float sc[2][4][4];
        #pragma unroll
        for (int mi = 0; mi < 2; mi++)
            #pragma unroll
            for (int ni = 0; ni < 4; ni++)
                #pragma unroll
                for (int r = 0; r < 4; r++) sc[mi][ni][r] = 0.f;

        #pragma unroll
        for (int kc = 0; kc < 8; kc++) {
            unsigned a[2][4], bb[4][2];
            #pragma unroll
            for (int mi = 0; mi < 2; mi++)
                ldsm4(a[mi], qbase + (unsigned)(mi*16*QSTR + kc*8) * 4u);
            #pragma unroll
            for (int np = 0; np < 2; np++) {
                unsigned t[4];
                ldsm4(t, kb + (unsigned)(np*16*QSTR + kc*8) * 4u);
                bb[2*np][0] = t[0]; bb[2*np][1] = t[1];
                bb[2*np+1][0] = t[2]; bb[2*np+1][1] = t[3];
            }
            #pragma unroll
            for (int mi = 0; mi < 2; mi++)
                #pragma unroll
                for (int ni = 0; ni < 4; ni++)
                    mma_tf32(sc[mi][ni], a[mi][0], a[mi][1], a[mi][2], a[mi][3],
                             bb[ni][0], bb[ni][1]);
        }

        // ---- mask(bits) + exp; unnormalized probs -> global(fp32) + Ps(tf32) ----
        #pragma unroll
        for (int mi = 0; mi < 2; mi++) {
            const int r0 = wm*32 + mi*16 + gr;
            #pragma unroll
            for (int ni = 0; ni < 4; ni++) {
                const int ck = wn*32 + ni*8 + 2*tg;
                const int bit = ni*8 + 2*tg;
                const size_t gcol = (size_t)kt*128 + ck;
                float p00 = (mw[mi][0] >> bit     & 1u) ? __expf(sc[mi][ni][0]) : 0.f;
                float p01 = (mw[mi][0] >> (bit+1) & 1u) ? __expf(sc[mi][ni][1]) : 0.f;
                float p10 = (mw[mi][1] >> bit     & 1u) ? __expf(sc[mi][ni][2]) : 0.f;
                float p11 = (mw[mi][1] >> (bit+1) & 1u) ? __expf(sc[mi][ni][3]) : 0.f;
                lacc[mi*2]   += p00 + p01;
                lacc[mi*2+1] += p10 + p11;
                *(float2*)&ab[(size_t)r0     * S_ + gcol] = make_float2(p00, p01);
                *(float2*)&ab[(size_t)(r0+8) * S_ + gcol] = make_float2(p10, p11);
                *(uint2*)&Ps[r0    *PSTR2 + ck] = make_uint2(f2tf(p00), f2tf(p01));
                *(uint2*)&Ps[(r0+8)*PSTR2 + ck] = make_uint2(f2tf(p10), f2tf(p11));
            }
        }
        cp_wait0();        // V[kt] (and K[kt+1]) landed — overlapped with scores+exp
        __syncthreads();   // P + V visible to all threads

        // ---- PV: warp tile 32q x 16d, k-dim = 128 keys ----
        #pragma unroll
        for (int kc = 0; kc < 16; kc++) {
            unsigned a2[2][4];
            ldsm4(a2[0], pbase + (unsigned)(kc*8) * 4u);
            ldsm4(a2[1], pbase + (unsigned)(16*PSTR2 + kc*8) * 4u);
            unsigned vb[2][2];
            #pragma unroll
            for (int f = 0; f < 2; f++) {
                const int d = wn2*16 + f*8 + gr;
                vb[f][0] = Vs[(kc*8 + tg    )*VSTR + d];
                vb[f][1] = Vs[(kc*8 + tg + 4)*VSTR + d];
            }
            #pragma unroll
            for (int mi = 0; mi < 2; mi++)
                #pragma unroll
                for (int f = 0; f < 2; f++)
                    mma_tf32(cacc[mi][f], a2[mi][0], a2[mi][1], a2[mi][2], a2[mi][3],
                             vb[f][0], vb[f][1]);
        }
    }

    // ---- row sums: quad shuffle reduce + cross-warp atomic ----
    #pragma unroll
    for (int i = 0; i < 4; i++) {
        float v = lacc[i];
        v += __shfl_xor_sync(0xffffffffu, v, 1);
        v += __shfl_xor_sync(0xffffffffu, v, 2);
        lacc[i] = v;
    }
    if (tg == 0) {
        #pragma unroll
        for (int mi = 0; mi < 2; mi++) {
            atomicAdd(&rowSum[wm*32 + mi*16 + gr],     lacc[mi*2]);
            atomicAdd(&rowSum[wm*32 + mi*16 + gr + 8], lacc[mi*2+1]);
        }
    }
    __syncthreads();
    if (tid < 128)
        g_invl[(size_t)bh * S_ + qt*128 + tid] = 1.0f / rowSum[tid];

    // ---- context write (scaled by 1/l), permuted to [b][s][h*64+d] ----
    #pragma unroll
    for (int mi = 0; mi < 2; mi++) {
        const int r0 = wm2*32 + mi*16 + gr;
        const float s0 = 1.0f / rowSum[r0];
        const float s1 = 1.0f / rowSum[r0 + 8];
        #pragma unroll
        for (int f = 0; f < 2; f++) {
            const int d = wn2*16 + f*8 + 2*tg;
            size_t d0 = ((size_t)(b*S_ + qt*128 + r0    )) * DM_ + h*DK_ + d;
            size_t d1 = ((size_t)(b*S_ + qt*128 + r0 + 8)) * DM_ + h*DK_ + d;
            *(float2*)&g_Ctx[d0] = make_float2(cacc[mi][f][0]*s0, cacc[mi][f][1]*s0);
            *(float2*)&g_Ctx[d1] = make_float2(cacc[mi][f][2]*s1, cacc[mi][f][3]*s1);
        }
    }
}

// ---------------------------------------------------------------------------
extern "C" void kernel_launch(void* const* d_in, const int* in_sizes, int n_in,
                              void* d_out, int out_size)
{
    const float* q    = (const float*)d_in[0];
    const float* k    = (const float*)d_in[1];
    const float* v    = (const float*)d_in[2];
    const int*   mask = (const int*)  d_in[3];
    const float* Wq   = (const float*)d_in[4];
    const float* Wk   = (const float*)d_in[5];
    const float* Wv   = (const float*)d_in[6];
    const float* Wo   = (const float*)d_in[7];
    const float* bo   = (const float*)d_in[8];

    float* out      = (float*)d_out;
    float* ctx_out  = out;                             // [B,S,DM]
    float* attn_out = out + (size_t)B_ * S_ * DM_;     // [B,H,S,S]

    void *pQ, *pK, *pV, *pC;
    cudaGetSymbolAddress(&pQ, g_Qh);
    cudaGetSymbolAddress(&pK, g_Kh);
    cudaGetSymbolAddress(&pV, g_Vh);
    cudaGetSymbolAddress(&pC, g_Ctx);

    const int smemAttn = SM_WORDS * 4;   // 209408
    cudaFuncSetAttribute(attn_mma, cudaFuncAttributeMaxDynamicSharedMemorySize, smemAttn);

    // All three QKV projections in ONE launch (1536 proj blocks, 3 GEMMs by
    // bid>>9) + 2048 mask-pack aux blocks filling the wave tail.
    proj_fused<<<1536 + 2048, 256>>>(q, Wq, (float*)pQ,
                                     k, Wk, (float*)pK,
                                     v, Wv, (float*)pV,
                                     nullptr, 1, 1, 1536, mask, nullptr);

    attn_mma<<<dim3(S_/128, B_*H_), 512, smemAttn>>>(attn_out);

    // Output projection (512 blocks) + attention rescale (2048 aux blocks)
    proj_fused<<<512 + 2048, 256>>>((const float*)pC, Wo, ctx_out,
                                    nullptr, nullptr, nullptr,
                                    nullptr, nullptr, nullptr,
                                    bo, 0, 2, 512, nullptr, attn_out);
}

// round 13
// speedup vs baseline: 1.2828x; 1.0552x over previous
#include <cuda_runtime.h>

#define B_  4
#define S_  2048
#define DM_ 1024
#define H_  16
#define DK_ 64
#define M_  (B_*S_)   // 8192 rows

// Scratch (allocation-free rule: __device__ globals)
__device__ float g_Qh[(size_t)B_*H_*S_*DK_];
__device__ float g_Kh[(size_t)B_*H_*S_*DK_];
__device__ float g_Vh[(size_t)B_*H_*S_*DK_];
__device__ float g_Ctx[(size_t)M_*DM_];
__device__ unsigned g_mbits[(size_t)B_*S_*(S_/32)];   // packed mask bits

// ---------------------------------------------------------------------------
// helpers
// ---------------------------------------------------------------------------
__device__ __forceinline__ unsigned f2tf(float x) {
    unsigned u;
    asm("cvt.rna.tf32.f32 %0, %1;" : "=r"(u) : "f"(x));
    return u;
}
__device__ __forceinline__ void mma_tf32(float c[4],
                                         unsigned a0, unsigned a1, unsigned a2, unsigned a3,
                                         unsigned b0, unsigned b1) {
    asm("mma.sync.aligned.m16n8k8.row.col.f32.tf32.tf32.f32 "
        "{%0,%1,%2,%3},{%4,%5,%6,%7},{%8,%9},{%0,%1,%2,%3};"
        : "+f"(c[0]), "+f"(c[1]), "+f"(c[2]), "+f"(c[3])
        : "r"(a0), "r"(a1), "r"(a2), "r"(a3), "r"(b0), "r"(b1));
}
__device__ __forceinline__ unsigned sm_u32(const void* p) {
    return (unsigned)__cvta_generic_to_shared(p);
}
__device__ __forceinline__ void ldsm4(unsigned r[4], unsigned addr) {
    asm volatile("ldmatrix.sync.aligned.m8n8.x4.shared.b16 {%0,%1,%2,%3}, [%4];"
        : "=r"(r[0]), "=r"(r[1]), "=r"(r[2]), "=r"(r[3]) : "r"(addr));
}
__device__ __forceinline__ void cp16(unsigned dst, const void* src) {
    asm volatile("cp.async.cg.shared.global [%0], [%1], 16;" :: "r"(dst), "l"(src));
}
__device__ __forceinline__ void cp_commit() {
    asm volatile("cp.async.commit_group;");
}
__device__ __forceinline__ void cp_wait0() {
    asm volatile("cp.async.wait_group 0;" ::: "memory");
}

// ---------------------------------------------------------------------------
// Fused projection GEMM (up to 3 independent GEMMs per launch, selected by
// bid>>9) + mask-pack aux work in blocks >= nProj.
// Proj: 128x128 tile, BK=32, 8 warps 2(m)x4(n), warp 64m x 32n.
// __launch_bounds__(256, 2) pins regs <= 128 (2 CTAs/SM).
// ---------------------------------------------------------------------------
#define XSTR 36
__global__ __launch_bounds__(256, 2) void proj_fused(
    const float* __restrict__ X0, const float* __restrict__ W0, float* __restrict__ Y0,
    const float* __restrict__ X1, const float* __restrict__ W1, float* __restrict__ Y1,
    const float* __restrict__ X2, const float* __restrict__ W2, float* __restrict__ Y2,
    const float* __restrict__ bias,
    int headsMode, int nProj,
    const int* __restrict__ mask)
{
    const int bid = blockIdx.x;
    if (bid >= nProj) {                // ---- pack mask bits ----
        const int aux = bid - nProj;
        const int lane = threadIdx.x & 31, w = threadIdx.x >> 5;
        size_t base = (size_t)aux * 256 + (size_t)w * 32;
        #pragma unroll 4
        for (int i = 0; i < 32; i++) {
            int m = mask[(base + i) * 32 + lane];
            unsigned bits = __ballot_sync(0xffffffffu, m != 0);
            if (lane == 0) g_mbits[base + i] = bits;
        }
        return;
    }

    const int which = bid >> 9;        // which GEMM (0..2)
    const int sub = bid & 511;
    const float* X = (which == 0) ? X0 : (which == 1) ? X1 : X2;
    const float* W = (which == 0) ? W0 : (which == 1) ? W1 : W2;
    float*       Y = (which == 0) ? Y0 : (which == 1) ? Y1 : Y2;

    __shared__ unsigned Xs[128 * XSTR];
    __shared__ unsigned Ws[128 * XSTR];
    const int tid = threadIdx.x;
    const int lane = tid & 31, wid = tid >> 5;
    const int wm = wid >> 2, wn = wid & 3;
    const int gr = lane >> 2, tg = lane & 3;
    const int m0 = (sub & 63) * 128, n0 = (sub >> 6) * 128;

    const int arow = lane & 15;
    const int acol = ((lane >> 4) & 1) * 4;
    const int brow = ((lane >> 4) & 1) * 8 + (lane & 7);
    const int bcol = ((lane >> 3) & 1) * 4;
    const unsigned abase = sm_u32(Xs + (wm*64 + arow)*XSTR + acol);
    const unsigned bbase = sm_u32(Ws + (wn*32 + brow)*XSTR + bcol);

    const int lr = tid >> 1;          // 0..127 (row)
    const int lh = (tid & 1) * 16;    // k-half

    float c[4][4][4];
    #pragma unroll
    for (int mi = 0; mi < 4; mi++)
        #pragma unroll
        for (int ni = 0; ni < 4; ni++)
            #pragma unroll
            for (int r = 0; r < 4; r++) c[mi][ni][r] = 0.f;

    const float* Xp = X + (size_t)(m0 + lr) * DM_ + lh;
    const float* Wp = W + (size_t)(n0 + lr) * DM_ + lh;

    float4 px[4], pw[4];
    #pragma unroll
    for (int j = 0; j < 4; j++) { px[j] = *(const float4*)(Xp + 4*j); pw[j] = *(const float4*)(Wp + 4*j); }

    #pragma unroll 1
    for (int it = 0; it < 32; it++) {
        #pragma unroll
        for (int j = 0; j < 4; j++) {
            *(uint4*)&Xs[lr*XSTR + lh + 4*j] = make_uint4(f2tf(px[j].x), f2tf(px[j].y), f2tf(px[j].z), f2tf(px[j].w));
            *(uint4*)&Ws[lr*XSTR + lh + 4*j] = make_uint4(f2tf(pw[j].x), f2tf(pw[j].y), f2tf(pw[j].z), f2tf(pw[j].w));
        }
        __syncthreads();

        if (it + 1 < 32) {
            const int ko = (it + 1) * 32;
            #pragma unroll
            for (int j = 0; j < 4; j++) { px[j] = *(const float4*)(Xp + ko + 4*j); pw[j] = *(const float4*)(Wp + ko + 4*j); }
        }

        #pragma unroll
        for (int kc = 0; kc < 4; kc++) {
            unsigned a[4][4], bb[4][2];
            #pragma unroll
            for (int mi = 0; mi < 4; mi++)
                ldsm4(a[mi], abase + (unsigned)(mi*16*XSTR + kc*8) * 4u);
            #pragma unroll
            for (int np = 0; np < 2; np++) {
                unsigned t[4];
                ldsm4(t, bbase + (unsigned)(np*16*XSTR + kc*8) * 4u);
                bb[2*np][0] = t[0]; bb[2*np][1] = t[1];
                bb[2*np+1][0] = t[2]; bb[2*np+1][1] = t[3];
            }
            #pragma unroll
            for (int mi = 0; mi < 4; mi++)
                #pragma unroll
                for (int ni = 0; ni < 4; ni++)
                    mma_tf32(c[mi][ni], a[mi][0], a[mi][1], a[mi][2], a[mi][3],
                             bb[ni][0], bb[ni][1]);
        }
        __syncthreads();
    }

    if (headsMode) {
        #pragma unroll
        for (int mi = 0; mi < 4; mi++) {
            int m = m0 + wm*64 + mi*16 + gr;
            int b = m >> 11, s = m & (S_ - 1);
            #pragma unroll
            for (int ni = 0; ni < 4; ni++) {
                int n = n0 + wn*32 + ni*8 + 2*tg;
                int h = n >> 6, dk = n & 63;
                size_t base = (((size_t)(b*H_ + h) * S_) + s) * DK_ + dk;
                *(float2*)&Y[base]         = make_float2(c[mi][ni][0], c[mi][ni][1]);
                *(float2*)&Y[base + 8*DK_] = make_float2(c[mi][ni][2], c[mi][ni][3]);
            }
        }
    } else {
        #pragma unroll
        for (int mi = 0; mi < 4; mi++) {
            int m = m0 + wm*64 + mi*16 + gr;
            #pragma unroll
            for (int ni = 0; ni < 4; ni++) {
                int n = n0 + wn*32 + ni*8 + 2*tg;
                float b0 = bias[n], b1 = bias[n+1];
                *(float2*)&Y[(size_t)m * DM_ + n] =
                    make_float2(c[mi][ni][0] + b0, c[mi][ni][1] + b1);
                *(float2*)&Y[(size_t)(m+8) * DM_ + n] =
                    make_float2(c[mi][ni][2] + b0, c[mi][ni][3] + b1);
            }
        }
    }
}

// ---------------------------------------------------------------------------
// Fused attention, 512 threads / 16 warps, TWO-PASS normalized output.
// Pass 1: pipelined K loads, scores + masked exp -> row sums only.
// Pass 2: pipelined K+V loads, scores recomputed, probs normalized by 1/l,
//         written once (fp32) to global, PV mma on normalized tf32 P.
// No rescale pass needed; context is already normalized.
// smem words: Qs 8704 | Ks0 8704 | Ks1 8704 | Vs 9216 | Ps 16896 | rowSum 128
// ---------------------------------------------------------------------------
#define QSTR 68
#define VSTR 72
#define PSTR2 132
#define OFF_KS0 8704
#define OFF_KS1 17408
#define OFF_VS  26112
#define OFF_PS  35328
#define OFF_RS  52224
#define SM_WORDS 52352
#define KBYTES (8704u * 4u)

__global__ __launch_bounds__(512) void attn_mma(float* __restrict__ attn)
{
    extern __shared__ unsigned smu[];
    unsigned* Qs = smu;
    unsigned* Ks = smu + OFF_KS0;  // two buffers of 8704 words
    unsigned* Vs = smu + OFF_VS;   // natural [key][d], stride 72
    unsigned* Ps = smu + OFF_PS;
    float* rowSum = (float*)(smu + OFF_RS);   // later holds 1/l

    const int tid = threadIdx.x;
    const int lane = tid & 31, wid = tid >> 5;
    const int wm = wid >> 2, wn = wid & 3;       // score map: 32q x 32k
    const int wm2 = wid & 3, wn2 = wid >> 2;     // PV map:    32q x 16d
    const int gr = lane >> 2, tg = lane & 3;
    const int qt = blockIdx.x, bh = blockIdx.y;
    const int b = bh >> 4, h = bh & 15;

    const int arow = lane & 15;
    const int acol = ((lane >> 4) & 1) * 4;
    const int brow = ((lane >> 4) & 1) * 8 + (lane & 7);
    const int bcol = ((lane >> 3) & 1) * 4;
    const unsigned qbase = sm_u32(Qs + (wm*32 + arow)*QSTR + acol);
    const unsigned kbase = sm_u32(Ks + (wn*32 + brow)*QSTR + bcol);
    const unsigned pbase = sm_u32(Ps + (wm2*32 + arow)*PSTR2 + acol);

    const float* Qb = g_Qh + ((size_t)bh * S_ + qt*128) * DK_;
    const float* Kb = g_Kh + (size_t)bh * S_ * DK_;
    const float* Vb = g_Vh + (size_t)bh * S_ * DK_;
    const unsigned* mbp = g_mbits + ((size_t)b * S_ + qt*128) * (S_/32);
    float* ab = attn + (size_t)bh * S_ * S_ + (size_t)qt * 128 * S_;

    if (tid < 128) rowSum[tid] = 0.f;

    const int lr = tid >> 2;            // 0..127
    const int seg = (tid & 3) * 16;     // d quarter
    const unsigned ksts = sm_u32(Ks + lr*QSTR + seg);
    const unsigned vsts = sm_u32(Vs + lr*VSTR + seg);

    { // Q load: scale by 1/sqrt(64), tf32 round (RNA)
        const float* qp = Qb + (size_t)lr * DK_ + seg;
        #pragma unroll
        for (int j = 0; j < 4; j++) {
            float4 v = *(const float4*)(qp + 4*j);
            *(uint4*)&Qs[lr*QSTR + seg + 4*j] =
                make_uint4(f2tf(v.x*0.125f), f2tf(v.y*0.125f),
                           f2tf(v.z*0.125f), f2tf(v.w*0.125f));
        }
    }
    { // prologue: K[0] into buffer 0
        const float* kp = Kb + (size_t)lr * DK_ + seg;
        #pragma unroll
        for (int j = 0; j < 4; j++) cp16(ksts + 16u*j, kp + 4*j);
        cp_commit();
        cp_wait0();
    }

    float lacc[4];
    #pragma unroll
    for (int i = 0; i < 4; i++) lacc[i] = 0.f;

    // ================= PASS 1: row sums only =================
    for (int kt = 0; kt < 16; kt++) {
        __syncthreads();   // all warps done with the buffer being overwritten; Qs/rowSum ready at kt=0
        if (kt + 1 < 16) {
            const float* kp = Kb + (size_t)((kt+1)*128 + lr) * DK_ + seg;
            const unsigned kdst = ksts + ((kt+1) & 1) * KBYTES;
            #pragma unroll
            for (int j = 0; j < 4; j++) cp16(kdst + 16u*j, kp + 4*j);
            cp_commit();
        }
        unsigned mw[2][2];
        #pragma unroll
        for (int mi = 0; mi < 2; mi++) {
            const int r0 = wm*32 + mi*16 + gr;
            mw[mi][0] = mbp[(size_t)r0      * (S_/32) + kt*4 + wn];
            mw[mi][1] = mbp[(size_t)(r0+8)  * (S_/32) + kt*4 + wn];
        }

        const unsigned kb = kbase + (kt & 1) * KBYTES;
        float sc[2][4][4];
        #pragma unroll
        for (int mi = 0; mi < 2; mi++)
            #pragma unroll
            for (int ni = 0; ni < 4; ni++)
                #pragma unroll
                for (int r = 0; r < 4; r++) sc[mi][ni][r] = 0.f;

        #pragma unroll
        for (int kc = 0; kc < 8; kc++) {
            unsigned a[2][4], bb[4][2];
            #pragma unroll
            for (int mi = 0; mi < 2; mi++)
                ldsm4(a[mi], qbase + (unsigned)(mi*16*QSTR + kc*8) * 4u);
            #pragma unroll
            for (int np = 0; np < 2; np++) {
                unsigned t[4];
                ldsm4(t, kb + (unsigned)(np*16*QSTR + kc*8) * 4u);
                bb[2*np][0] = t[0]; bb[2*np][1] = t[1];
                bb[2*np+1][0] = t[2]; bb[2*np+1][1] = t[3];
            }
            #pragma unroll
            for (int mi = 0; mi < 2; mi++)
                #pragma unroll
                for (int ni = 0; ni < 4; ni++)
                    mma_tf32(sc[mi][ni], a[mi][0], a[mi][1], a[mi][2], a[mi][3],
                             bb[ni][0], bb[ni][1]);
        }

        #pragma unroll
        for (int mi = 0; mi < 2; mi++) {
            #pragma unroll
            for (int ni = 0; ni < 4; ni++) {
                const int bit = ni*8 + 2*tg;
                float p00 = (mw[mi][0] >> bit     & 1u) ? __expf(sc[mi][ni][0]) : 0.f;
                float p01 = (mw[mi][0] >> (bit+1) & 1u) ? __expf(sc[mi][ni][1]) : 0.f;
                float p10 = (mw[mi][1] >> bit     & 1u) ? __expf(sc[mi][ni][2]) : 0.f;
                float p11 = (mw[mi][1] >> (bit+1) & 1u) ? __expf(sc[mi][ni][3]) : 0.f;
                lacc[mi*2]   += p00 + p01;
                lacc[mi*2+1] += p10 + p11;
            }
        }
        cp_wait0();        // K[kt+1] landed, overlapped with scores+exp
    }

    // ---- reduce row sums; rowSum becomes 1/l ----
    #pragma unroll
    for (int i = 0; i < 4; i++) {
        float v = lacc[i];
        v += __shfl_xor_sync(0xffffffffu, v, 1);
        v += __shfl_xor_sync(0xffffffffu, v, 2);
        lacc[i] = v;
    }
    if (tg == 0) {
        #pragma unroll
        for (int mi = 0; mi < 2; mi++) {
            atomicAdd(&rowSum[wm*32 + mi*16 + gr],     lacc[mi*2]);
            atomicAdd(&rowSum[wm*32 + mi*16 + gr + 8], lacc[mi*2+1]);
        }
    }
    __syncthreads();
    if (tid < 128) rowSum[tid] = 1.0f / rowSum[tid];
    __syncthreads();

    // per-thread invl for this thread's score rows
    float inv0[2], inv1[2];
    #pragma unroll
    for (int mi = 0; mi < 2; mi++) {
        inv0[mi] = rowSum[wm*32 + mi*16 + gr];
        inv1[mi] = rowSum[wm*32 + mi*16 + gr + 8];
    }

    { // pass-2 prologue: K[0] into buffer 0
        const float* kp = Kb + (size_t)lr * DK_ + seg;
        #pragma unroll
        for (int j = 0; j < 4; j++) cp16(ksts + 16u*j, kp + 4*j);
        cp_commit();
        cp_wait0();
    }

    float cacc[2][2][4];
    #pragma unroll
    for (int mi = 0; mi < 2; mi++)
        #pragma unroll
        for (int f = 0; f < 2; f++)
            #pragma unroll
            for (int r = 0; r < 4; r++) cacc[mi][f][r] = 0.f;

    // ================= PASS 2: normalized probs + PV =================
    for (int kt = 0; kt < 16; kt++) {
        __syncthreads();   // prev PV done with Vs/Ps; K[kt] visible
        {
            const float* vp = Vb + (size_t)(kt*128 + lr) * DK_ + seg;
            #pragma unroll
            for (int j = 0; j < 4; j++) cp16(vsts + 16u*j, vp + 4*j);
            if (kt + 1 < 16) {
                const float* kp = Kb + (size_t)((kt+1)*128 + lr) * DK_ + seg;
                const unsigned kdst = ksts + ((kt+1) & 1) * KBYTES;
                #pragma unroll
                for (int j = 0; j < 4; j++) cp16(kdst + 16u*j, kp + 4*j);
            }
            cp_commit();
        }
        unsigned mw[2][2];
        #pragma unroll
        for (int mi = 0; mi < 2; mi++) {
            const int r0 = wm*32 + mi*16 + gr;
            mw[mi][0] = mbp[(size_t)r0      * (S_/32) + kt*4 + wn];
            mw[mi][1] = mbp[(size_t)(r0+8)  * (S_/32) + kt*4 + wn];
        }

        const unsigned kb = kbase + (kt & 1) * KBYTES;
        float sc[2][4][4];
        #pragma unroll
        for (int mi = 0; mi < 2; mi++)
            #pragma unroll
            for (int ni = 0; ni < 4; ni++)
                #pragma unroll
                for (int r = 0; r < 4; r++) sc[mi][ni][r] = 0.f;

        #pragma unroll
        for (int kc = 0; kc < 8; kc++) {
            unsigned a[2][4], bb[4][2];
            #pragma unroll
            for (int mi = 0; mi < 2; mi++)
                ldsm4(a[mi], qbase + (unsigned)(mi*16*QSTR + kc*8) * 4u);
            #pragma unroll
            for (int np = 0; np < 2; np++) {
                unsigned t[4];
                ldsm4(t, kb + (unsigned)(np*16*QSTR + kc*8) * 4u);
                bb[2*np][0] = t[0]; bb[2*np][1] = t[1];
                bb[2*np+1][0] = t[2]; bb[2*np+1][1] = t[3];
            }
            #pragma unroll
            for (int mi = 0; mi < 2; mi++)
                #pragma unroll
                for (int ni = 0; ni < 4; ni++)
                    mma_tf32(sc[mi][ni], a[mi][0], a[mi][1], a[mi][2], a[mi][3],
                             bb[ni][0], bb[ni][1]);
        }

        // mask + exp, normalized by invl; write final probs + Ps (tf32)
        #pragma unroll
        for (int mi = 0; mi < 2; mi++) {
            const int r0 = wm*32 + mi*16 + gr;
            #pragma unroll
            for (int ni = 0; ni < 4; ni++) {
                const int ck = wn*32 + ni*8 + 2*tg;
                const int bit = ni*8 + 2*tg;
                const size_t gcol = (size_t)kt*128 + ck;
                float p00 = (mw[mi][0] >> bit     & 1u) ? __expf(sc[mi][ni][0]) * inv0[mi] : 0.f;
                float p01 = (mw[mi][0] >> (bit+1) & 1u) ? __expf(sc[mi][ni][1]) * inv0[mi] : 0.f;
                float p10 = (mw[mi][1] >> bit     & 1u) ? __expf(sc[mi][ni][2]) * inv1[mi] : 0.f;
                float p11 = (mw[mi][1] >> (bit+1) & 1u) ? __expf(sc[mi][ni][3]) * inv1[mi] : 0.f;
                *(float2*)&ab[(size_t)r0     * S_ + gcol] = make_float2(p00, p01);
                *(float2*)&ab[(size_t)(r0+8) * S_ + gcol] = make_float2(p10, p11);
                *(uint2*)&Ps[r0    *PSTR2 + ck] = make_uint2(f2tf(p00), f2tf(p01));
                *(uint2*)&Ps[(r0+8)*PSTR2 + ck] = make_uint2(f2tf(p10), f2tf(p11));
            }
        }
        cp_wait0();        // V[kt] (and K[kt+1]) landed — overlapped with scores+exp
        __syncthreads();   // P + V visible to all threads

        // ---- PV: warp tile 32q x 16d, k-dim = 128 keys ----
        #pragma unroll
        for (int kc = 0; kc < 16; kc++) {
            unsigned a2[2][4];
            ldsm4(a2[0], pbase + (unsigned)(kc*8) * 4u);
            ldsm4(a2[1], pbase + (unsigned)(16*PSTR2 + kc*8) * 4u);
            unsigned vb[2][2];
            #pragma unroll
            for (int f = 0; f < 2; f++) {
                const int d = wn2*16 + f*8 + gr;
                vb[f][0] = Vs[(kc*8 + tg    )*VSTR + d];
                vb[f][1] = Vs[(kc*8 + tg + 4)*VSTR + d];
            }
            #pragma unroll
            for (int mi = 0; mi < 2; mi++)
                #pragma unroll
                for (int f = 0; f < 2; f++)
                    mma_tf32(cacc[mi][f], a2[mi][0], a2[mi][1], a2[mi][2], a2[mi][3],
                             vb[f][0], vb[f][1]);
        }
    }

    // ---- context write (already normalized), permuted to [b][s][h*64+d] ----
    #pragma unroll
    for (int mi = 0; mi < 2; mi++) {
        const int r0 = wm2*32 + mi*16 + gr;
        #pragma unroll
        for (int f = 0; f < 2; f++) {
            const int d = wn2*16 + f*8 + 2*tg;
            size_t d0 = ((size_t)(b*S_ + qt*128 + r0    )) * DM_ + h*DK_ + d;
            size_t d1 = ((size_t)(b*S_ + qt*128 + r0 + 8)) * DM_ + h*DK_ + d;
            *(float2*)&g_Ctx[d0] = make_float2(cacc[mi][f][0], cacc[mi][f][1]);
            *(float2*)&g_Ctx[d1] = make_float2(cacc[mi][f][2], cacc[mi][f][3]);
        }
    }
}

// ---------------------------------------------------------------------------
extern "C" void kernel_launch(void* const* d_in, const int* in_sizes, int n_in,
                              void* d_out, int out_size)
{
    const float* q    = (const float*)d_in[0];
    const float* k    = (const float*)d_in[1];
    const float* v    = (const float*)d_in[2];
    const int*   mask = (const int*)  d_in[3];
    const float* Wq   = (const float*)d_in[4];
    const float* Wk   = (const float*)d_in[5];
    const float* Wv   = (const float*)d_in[6];
    const float* Wo   = (const float*)d_in[7];
    const float* bo   = (const float*)d_in[8];

    float* out      = (float*)d_out;
    float* ctx_out  = out;                             // [B,S,DM]
    float* attn_out = out + (size_t)B_ * S_ * DM_;     // [B,H,S,S]

    void *pQ, *pK, *pV, *pC;
    cudaGetSymbolAddress(&pQ, g_Qh);
    cudaGetSymbolAddress(&pK, g_Kh);
    cudaGetSymbolAddress(&pV, g_Vh);
    cudaGetSymbolAddress(&pC, g_Ctx);

    const int smemAttn = SM_WORDS * 4;   // 209408
    cudaFuncSetAttribute(attn_mma, cudaFuncAttributeMaxDynamicSharedMemorySize, smemAttn);

    // All three QKV projections in ONE launch (1536 proj blocks, 3 GEMMs by
    // bid>>9) + 2048 mask-pack aux blocks filling the wave tail.
    proj_fused<<<1536 + 2048, 256>>>(q, Wq, (float*)pQ,
                                     k, Wk, (float*)pK,
                                     v, Wv, (float*)pV,
                                     nullptr, 1, 1536, mask);

    attn_mma<<<dim3(S_/128, B_*H_), 512, smemAttn>>>(attn_out);

    // Output projection only — attention is written normalized, no rescale.
    proj_fused<<<512, 256>>>((const float*)pC, Wo, ctx_out,
                             nullptr, nullptr, nullptr,
                             nullptr, nullptr, nullptr,
                             bo, 0, 512, nullptr);
}

// round 14
// speedup vs baseline: 1.4585x; 1.1369x over previous
#include <cuda_runtime.h>
#include <cuda_fp16.h>

#define B_  4
#define S_  2048
#define DM_ 1024
#define H_  16
#define DK_ 64
#define M_  (B_*S_)   // 8192 rows

// Scratch (allocation-free rule: __device__ globals)
__device__ __half g_Qh[(size_t)B_*H_*S_*DK_];   // fp16, pre-scaled by 1/8
__device__ __half g_Kh[(size_t)B_*H_*S_*DK_];   // fp16
__device__ float  g_Vh[(size_t)B_*H_*S_*DK_];   // fp32 (PV path unchanged)
__device__ float  g_Ctx[(size_t)M_*DM_];
__device__ unsigned g_mbits[(size_t)B_*S_*(S_/32)];   // packed mask bits

// ---------------------------------------------------------------------------
// helpers
// ---------------------------------------------------------------------------
__device__ __forceinline__ unsigned f2tf(float x) {
    unsigned u;
    asm("cvt.rna.tf32.f32 %0, %1;" : "=r"(u) : "f"(x));
    return u;
}
__device__ __forceinline__ unsigned pk_h2(float lo, float hi) {
    unsigned u;
    asm("cvt.rn.f16x2.f32 %0, %1, %2;" : "=r"(u) : "f"(hi), "f"(lo));
    return u;
}
__device__ __forceinline__ void mma_tf32(float c[4],
                                         unsigned a0, unsigned a1, unsigned a2, unsigned a3,
                                         unsigned b0, unsigned b1) {
    asm("mma.sync.aligned.m16n8k8.row.col.f32.tf32.tf32.f32 "
        "{%0,%1,%2,%3},{%4,%5,%6,%7},{%8,%9},{%0,%1,%2,%3};"
        : "+f"(c[0]), "+f"(c[1]), "+f"(c[2]), "+f"(c[3])
        : "r"(a0), "r"(a1), "r"(a2), "r"(a3), "r"(b0), "r"(b1));
}
__device__ __forceinline__ void mma_f16(float c[4],
                                        unsigned a0, unsigned a1, unsigned a2, unsigned a3,
                                        unsigned b0, unsigned b1) {
    asm("mma.sync.aligned.m16n8k16.row.col.f32.f16.f16.f32 "
        "{%0,%1,%2,%3},{%4,%5,%6,%7},{%8,%9},{%0,%1,%2,%3};"
        : "+f"(c[0]), "+f"(c[1]), "+f"(c[2]), "+f"(c[3])
        : "r"(a0), "r"(a1), "r"(a2), "r"(a3), "r"(b0), "r"(b1));
}
__device__ __forceinline__ unsigned sm_u32(const void* p) {
    return (unsigned)__cvta_generic_to_shared(p);
}
__device__ __forceinline__ void ldsm4(unsigned r[4], unsigned addr) {
    asm volatile("ldmatrix.sync.aligned.m8n8.x4.shared.b16 {%0,%1,%2,%3}, [%4];"
        : "=r"(r[0]), "=r"(r[1]), "=r"(r[2]), "=r"(r[3]) : "r"(addr));
}
__device__ __forceinline__ void cp16(unsigned dst, const void* src) {
    asm volatile("cp.async.cg.shared.global [%0], [%1], 16;" :: "r"(dst), "l"(src));
}
__device__ __forceinline__ void cp_commit() {
    asm volatile("cp.async.commit_group;");
}
__device__ __forceinline__ void cp_wait0() {
    asm volatile("cp.async.wait_group 0;" ::: "memory");
}

// ---------------------------------------------------------------------------
// Fused projection GEMM (up to 3 GEMMs per launch by bid>>9) + mask-pack aux.
// Proj: 128x128 tile, BK=32, 8 warps 2(m)x4(n), warp 64m x 32n.
// __launch_bounds__(256, 2) pins regs <= 128 (2 CTAs/SM).
// headsMode: which 0 -> fp16 out scaled 1/8 (Q); which 1 -> fp16 (K);
//            which 2 -> fp32 (V). headsMode=0: flat fp32 + bias.
// ---------------------------------------------------------------------------
#define XSTR 36
__global__ __launch_bounds__(256, 2) void proj_fused(
    const float* __restrict__ X0, const float* __restrict__ W0, float* __restrict__ Y0,
    const float* __restrict__ X1, const float* __restrict__ W1, float* __restrict__ Y1,
    const float* __restrict__ X2, const float* __restrict__ W2, float* __restrict__ Y2,
    const float* __restrict__ bias,
    int headsMode, int nProj,
    const int* __restrict__ mask)
{
    const int bid = blockIdx.x;
    if (bid >= nProj) {                // ---- pack mask bits ----
        const int aux = bid - nProj;
        const int lane = threadIdx.x & 31, w = threadIdx.x >> 5;
        size_t base = (size_t)aux * 256 + (size_t)w * 32;
        #pragma unroll 4
        for (int i = 0; i < 32; i++) {
            int m = mask[(base + i) * 32 + lane];
            unsigned bits = __ballot_sync(0xffffffffu, m != 0);
            if (lane == 0) g_mbits[base + i] = bits;
        }
        return;
    }

    const int which = bid >> 9;        // which GEMM (0..2)
    const int sub = bid & 511;
    const float* X = (which == 0) ? X0 : (which == 1) ? X1 : X2;
    const float* W = (which == 0) ? W0 : (which == 1) ? W1 : W2;
    float*       Y = (which == 0) ? Y0 : (which == 1) ? Y1 : Y2;

    __shared__ unsigned Xs[128 * XSTR];
    __shared__ unsigned Ws[128 * XSTR];
    const int tid = threadIdx.x;
    const int lane = tid & 31, wid = tid >> 5;
    const int wm = wid >> 2, wn = wid & 3;
    const int gr = lane >> 2, tg = lane & 3;
    const int m0 = (sub & 63) * 128, n0 = (sub >> 6) * 128;

    const int arow = lane & 15;
    const int acol = ((lane >> 4) & 1) * 4;
    const int brow = ((lane >> 4) & 1) * 8 + (lane & 7);
    const int bcol = ((lane >> 3) & 1) * 4;
    const unsigned abase = sm_u32(Xs + (wm*64 + arow)*XSTR + acol);
    const unsigned bbase = sm_u32(Ws + (wn*32 + brow)*XSTR + bcol);

    const int lr = tid >> 1;          // 0..127 (row)
    const int lh = (tid & 1) * 16;    // k-half

    float c[4][4][4];
    #pragma unroll
    for (int mi = 0; mi < 4; mi++)
        #pragma unroll
        for (int ni = 0; ni < 4; ni++)
            #pragma unroll
            for (int r = 0; r < 4; r++) c[mi][ni][r] = 0.f;

    const float* Xp = X + (size_t)(m0 + lr) * DM_ + lh;
    const float* Wp = W + (size_t)(n0 + lr) * DM_ + lh;

    float4 px[4], pw[4];
    #pragma unroll
    for (int j = 0; j < 4; j++) { px[j] = *(const float4*)(Xp + 4*j); pw[j] = *(const float4*)(Wp + 4*j); }

    #pragma unroll 1
    for (int it = 0; it < 32; it++) {
        #pragma unroll
        for (int j = 0; j < 4; j++) {
            *(uint4*)&Xs[lr*XSTR + lh + 4*j] = make_uint4(f2tf(px[j].x), f2tf(px[j].y), f2tf(px[j].z), f2tf(px[j].w));
            *(uint4*)&Ws[lr*XSTR + lh + 4*j] = make_uint4(f2tf(pw[j].x), f2tf(pw[j].y), f2tf(pw[j].z), f2tf(pw[j].w));
        }
        __syncthreads();

        if (it + 1 < 32) {
            const int ko = (it + 1) * 32;
            #pragma unroll
            for (int j = 0; j < 4; j++) { px[j] = *(const float4*)(Xp + ko + 4*j); pw[j] = *(const float4*)(Wp + ko + 4*j); }
        }

        #pragma unroll
        for (int kc = 0; kc < 4; kc++) {
            unsigned a[4][4], bb[4][2];
            #pragma unroll
            for (int mi = 0; mi < 4; mi++)
                ldsm4(a[mi], abase + (unsigned)(mi*16*XSTR + kc*8) * 4u);
            #pragma unroll
            for (int np = 0; np < 2; np++) {
                unsigned t[4];
                ldsm4(t, bbase + (unsigned)(np*16*XSTR + kc*8) * 4u);
                bb[2*np][0] = t[0]; bb[2*np][1] = t[1];
                bb[2*np+1][0] = t[2]; bb[2*np+1][1] = t[3];
            }
            #pragma unroll
            for (int mi = 0; mi < 4; mi++)
                #pragma unroll
                for (int ni = 0; ni < 4; ni++)
                    mma_tf32(c[mi][ni], a[mi][0], a[mi][1], a[mi][2], a[mi][3],
                             bb[ni][0], bb[ni][1]);
        }
        __syncthreads();
    }

    if (headsMode) {
        const float s = (which == 0) ? 0.125f : 1.0f;
        #pragma unroll
        for (int mi = 0; mi < 4; mi++) {
            int m = m0 + wm*64 + mi*16 + gr;
            int b = m >> 11, sq = m & (S_ - 1);
            #pragma unroll
            for (int ni = 0; ni < 4; ni++) {
                int n = n0 + wn*32 + ni*8 + 2*tg;
                int h = n >> 6, dk = n & 63;
                size_t base = (((size_t)(b*H_ + h) * S_) + sq) * DK_ + dk;
                if (which < 2) {
                    __half* Yh = (__half*)Y;
                    *(unsigned*)&Yh[base] =
                        pk_h2(c[mi][ni][0]*s, c[mi][ni][1]*s);
                    *(unsigned*)&Yh[base + 8*DK_] =
                        pk_h2(c[mi][ni][2]*s, c[mi][ni][3]*s);
                } else {
                    *(float2*)&Y[base]         = make_float2(c[mi][ni][0], c[mi][ni][1]);
                    *(float2*)&Y[base + 8*DK_] = make_float2(c[mi][ni][2], c[mi][ni][3]);
                }
            }
        }
    } else {
        #pragma unroll
        for (int mi = 0; mi < 4; mi++) {
            int m = m0 + wm*64 + mi*16 + gr;
            #pragma unroll
            for (int ni = 0; ni < 4; ni++) {
                int n = n0 + wn*32 + ni*8 + 2*tg;
                float b0 = bias[n], b1 = bias[n+1];
                *(float2*)&Y[(size_t)m * DM_ + n] =
                    make_float2(c[mi][ni][0] + b0, c[mi][ni][1] + b1);
                *(float2*)&Y[(size_t)(m+8) * DM_ + n] =
                    make_float2(c[mi][ni][2] + b0, c[mi][ni][3] + b1);
            }
        }
    }
}

// ---------------------------------------------------------------------------
// Fused attention, 512 threads / 16 warps, TWO-PASS normalized output.
// Scores: fp16 m16n8k16 (Q,K fp16 from proj), warps 4x4, warp 32q x 32k.
// PV: tf32 m16n8k8 (P tf32 smem, V fp32 cp.async), warps 4x4, warp 32q x 16d.
// K double-buffered cp.async (fp16 = half the bytes); V cp.async in pass 2.
// smem words: Qs(h) 4608 | Ks(h) 2x4608 | Vs 9216 | Ps 16896 | rowSum 128
// ---------------------------------------------------------------------------
#define QSTRH 36      // words per 64-half row (32 + 4 pad)
#define VSTR 72
#define PSTR2 132
#define OFF_KS 4608
#define OFF_VS 13824
#define OFF_PS 23040
#define OFF_RS 39936
#define SM_WORDS 40064
#define KBYTES (4608u * 4u)

__global__ __launch_bounds__(512) void attn_mma(float* __restrict__ attn)
{
    extern __shared__ unsigned smu[];
    unsigned* Qs = smu;            // fp16 [q][d], stride 36 words
    unsigned* Ks = smu + OFF_KS;   // fp16, two buffers of 4608 words
    unsigned* Vs = smu + OFF_VS;   // fp32 [key][d], stride 72
    unsigned* Ps = smu + OFF_PS;   // tf32 [q][k], stride 132
    float* rowSum = (float*)(smu + OFF_RS);   // later holds 1/l

    const int tid = threadIdx.x;
    const int lane = tid & 31, wid = tid >> 5;
    const int wm = wid >> 2, wn = wid & 3;       // score map: 32q x 32k
    const int wm2 = wid & 3, wn2 = wid >> 2;     // PV map:    32q x 16d
    const int gr = lane >> 2, tg = lane & 3;
    const int qt = blockIdx.x, bh = blockIdx.y;
    const int b = bh >> 4, h = bh & 15;

    // fp16 ldsm addressing (16B = 4 words per col-half)
    const unsigned qbase = sm_u32(Qs + (wm*32 + (lane & 15))*QSTRH + ((lane >> 4) & 1)*4);
    const unsigned kbase = sm_u32(Ks + (wn*32 + (lane & 7) + ((lane >> 3) & 1)*8)*QSTRH
                                     + ((lane >> 4) & 1)*4);
    // PV (tf32) addressing, unchanged
    const int arow = lane & 15;
    const int acol = ((lane >> 4) & 1) * 4;
    const unsigned pbase = sm_u32(Ps + (wm2*32 + arow)*PSTR2 + acol);

    const __half* Qb = g_Qh + ((size_t)bh * S_ + qt*128) * DK_;
    const __half* Kb = g_Kh + (size_t)bh * S_ * DK_;
    const float*  Vb = g_Vh + (size_t)bh * S_ * DK_;
    const unsigned* mbp = g_mbits + ((size_t)b * S_ + qt*128) * (S_/32);
    float* ab = attn + (size_t)bh * S_ * S_ + (size_t)qt * 128 * S_;

    if (tid < 128) rowSum[tid] = 0.f;

    const int lr = tid >> 2;            // 0..127
    const int segh = (tid & 3) * 16;    // d quarter in halves
    const int segf = (tid & 3) * 16;    // d quarter in floats (V)
    const unsigned qsts = sm_u32(Qs + lr*QSTRH + (segh >> 1));
    const unsigned ksts = sm_u32(Ks + lr*QSTRH + (segh >> 1));
    const unsigned vsts = sm_u32(Vs + lr*VSTR + segf);

    { // prologue: Q tile + K[0] via cp.async (both fp16: 2x16B each)
        const __half* qp = Qb + (size_t)lr * DK_ + segh;
        const __half* kp = Kb + (size_t)lr * DK_ + segh;
        cp16(qsts,       qp);
        cp16(qsts + 16u, qp + 8);
        cp16(ksts,       kp);
        cp16(ksts + 16u, kp + 8);
        cp_commit();
        cp_wait0();
    }

    float lacc[4];
    #pragma unroll
    for (int i = 0; i < 4; i++) lacc[i] = 0.f;

    // ================= PASS 1: row sums only =================
    for (int kt = 0; kt < 16; kt++) {
        __syncthreads();   // buffer being overwritten free; Qs/rowSum ready at kt=0
        if (kt + 1 < 16) {
            const __half* kp = Kb + (size_t)((kt+1)*128 + lr) * DK_ + segh;
            const unsigned kdst = ksts + ((kt+1) & 1) * KBYTES;
            cp16(kdst,       kp);
            cp16(kdst + 16u, kp + 8);
            cp_commit();
        }
        unsigned mw[2][2];
        #pragma unroll
        for (int mi = 0; mi < 2; mi++) {
            const int r0 = wm*32 + mi*16 + gr;
            mw[mi][0] = mbp[(size_t)r0      * (S_/32) + kt*4 + wn];
            mw[mi][1] = mbp[(size_t)(r0+8)  * (S_/32) + kt*4 + wn];
        }

        const unsigned kb = kbase + (kt & 1) * KBYTES;
        float sc[2][4][4];
        #pragma unroll
        for (int mi = 0; mi < 2; mi++)
            #pragma unroll
            for (int ni = 0; ni < 4; ni++)
                #pragma unroll
                for (int r = 0; r < 4; r++) sc[mi][ni][r] = 0.f;

        #pragma unroll
        for (int kc = 0; kc < 4; kc++) {          // k16 per step
            unsigned a[2][4], bbf[4][2];
            ldsm4(a[0], qbase + (unsigned)(kc*8) * 4u);
            ldsm4(a[1], qbase + (unsigned)(16*QSTRH + kc*8) * 4u);
            #pragma unroll
            for (int np = 0; np < 2; np++) {
                unsigned t[4];
                ldsm4(t, kb + (unsigned)(np*16*QSTRH + kc*8) * 4u);
                bbf[2*np][0]   = t[0]; bbf[2*np][1]   = t[2];
                bbf[2*np+1][0] = t[1]; bbf[2*np+1][1] = t[3];
            }
            #pragma unroll
            for (int mi = 0; mi < 2; mi++)
                #pragma unroll
                for (int ni = 0; ni < 4; ni++)
                    mma_f16(sc[mi][ni], a[mi][0], a[mi][1], a[mi][2], a[mi][3],
                            bbf[ni][0], bbf[ni][1]);
        }

        #pragma unroll
        for (int mi = 0; mi < 2; mi++) {
            #pragma unroll
            for (int ni = 0; ni < 4; ni++) {
                const int bit = ni*8 + 2*tg;
                float p00 = (mw[mi][0] >> bit     & 1u) ? __expf(sc[mi][ni][0]) : 0.f;
                float p01 = (mw[mi][0] >> (bit+1) & 1u) ? __expf(sc[mi][ni][1]) : 0.f;
                float p10 = (mw[mi][1] >> bit     & 1u) ? __expf(sc[mi][ni][2]) : 0.f;
                float p11 = (mw[mi][1] >> (bit+1) & 1u) ? __expf(sc[mi][ni][3]) : 0.f;
                lacc[mi*2]   += p00 + p01;
                lacc[mi*2+1] += p10 + p11;
            }
        }
        cp_wait0();        // K[kt+1] landed, overlapped with scores+exp
    }

    // ---- reduce row sums; rowSum becomes 1/l ----
    #pragma unroll
    for (int i = 0; i < 4; i++) {
        float v = lacc[i];
        v += __shfl_xor_sync(0xffffffffu, v, 1);
        v += __shfl_xor_sync(0xffffffffu, v, 2);
        lacc[i] = v;
    }
    if (tg == 0) {
        #pragma unroll
        for (int mi = 0; mi < 2; mi++) {
            atomicAdd(&rowSum[wm*32 + mi*16 + gr],     lacc[mi*2]);
            atomicAdd(&rowSum[wm*32 + mi*16 + gr + 8], lacc[mi*2+1]);
        }
    }
    __syncthreads();
    if (tid < 128) rowSum[tid] = 1.0f / rowSum[tid];
    __syncthreads();

    float inv0[2], inv1[2];
    #pragma unroll
    for (int mi = 0; mi < 2; mi++) {
        inv0[mi] = rowSum[wm*32 + mi*16 + gr];
        inv1[mi] = rowSum[wm*32 + mi*16 + gr + 8];
    }

    { // pass-2 prologue: K[0] into buffer 0
        const __half* kp = Kb + (size_t)lr * DK_ + segh;
        cp16(ksts,       kp);
        cp16(ksts + 16u, kp + 8);
        cp_commit();
        cp_wait0();
    }

    float cacc[2][2][4];
    #pragma unroll
    for (int mi = 0; mi < 2; mi++)
        #pragma unroll
        for (int f = 0; f < 2; f++)
            #pragma unroll
            for (int r = 0; r < 4; r++) cacc[mi][f][r] = 0.f;

    // ================= PASS 2: normalized probs + PV =================
    for (int kt = 0; kt < 16; kt++) {
        __syncthreads();   // prev PV done with Vs/Ps; K[kt] visible
        {
            const float* vp = Vb + (size_t)(kt*128 + lr) * DK_ + segf;
            #pragma unroll
            for (int j = 0; j < 4; j++) cp16(vsts + 16u*j, vp + 4*j);
            if (kt + 1 < 16) {
                const __half* kp = Kb + (size_t)((kt+1)*128 + lr) * DK_ + segh;
                const unsigned kdst = ksts + ((kt+1) & 1) * KBYTES;
                cp16(kdst,       kp);
                cp16(kdst + 16u, kp + 8);
            }
            cp_commit();
        }
        unsigned mw[2][2];
        #pragma unroll
        for (int mi = 0; mi < 2; mi++) {
            const int r0 = wm*32 + mi*16 + gr;
            mw[mi][0] = mbp[(size_t)r0      * (S_/32) + kt*4 + wn];
            mw[mi][1] = mbp[(size_t)(r0+8)  * (S_/32) + kt*4 + wn];
        }

        const unsigned kb = kbase + (kt & 1) * KBYTES;
        float sc[2][4][4];
        #pragma unroll
        for (int mi = 0; mi < 2; mi++)
            #pragma unroll
            for (int ni = 0; ni < 4; ni++)
                #pragma unroll
                for (int r = 0; r < 4; r++) sc[mi][ni][r] = 0.f;

        #pragma unroll
        for (int kc = 0; kc < 4; kc++) {
            unsigned a[2][4], bbf[4][2];
            ldsm4(a[0], qbase + (unsigned)(kc*8) * 4u);
            ldsm4(a[1], qbase + (unsigned)(16*QSTRH + kc*8) * 4u);
            #pragma unroll
            for (int np = 0; np < 2; np++) {
                unsigned t[4];
                ldsm4(t, kb + (unsigned)(np*16*QSTRH + kc*8) * 4u);
                bbf[2*np][0]   = t[0]; bbf[2*np][1]   = t[2];
                bbf[2*np+1][0] = t[1]; bbf[2*np+1][1] = t[3];
            }
            #pragma unroll
            for (int mi = 0; mi < 2; mi++)
                #pragma unroll
                for (int ni = 0; ni < 4; ni++)
                    mma_f16(sc[mi][ni], a[mi][0], a[mi][1], a[mi][2], a[mi][3],
                            bbf[ni][0], bbf[ni][1]);
        }

        // mask + exp, normalized; write final probs + Ps (tf32)
        #pragma unroll
        for (int mi = 0; mi < 2; mi++) {
            const int r0 = wm*32 + mi*16 + gr;
            #pragma unroll
            for (int ni = 0; ni < 4; ni++) {
                const int ck = wn*32 + ni*8 + 2*tg;
                const int bit = ni*8 + 2*tg;
                const size_t gcol = (size_t)kt*128 + ck;
                float p00 = (mw[mi][0] >> bit     & 1u) ? __expf(sc[mi][ni][0]) * inv0[mi] : 0.f;
                float p01 = (mw[mi][0] >> (bit+1) & 1u) ? __expf(sc[mi][ni][1]) * inv0[mi] : 0.f;
                float p10 = (mw[mi][1] >> bit     & 1u) ? __expf(sc[mi][ni][2]) * inv1[mi] : 0.f;
                float p11 = (mw[mi][1] >> (bit+1) & 1u) ? __expf(sc[mi][ni][3]) * inv1[mi] : 0.f;
                *(float2*)&ab[(size_t)r0     * S_ + gcol] = make_float2(p00, p01);
                *(float2*)&ab[(size_t)(r0+8) * S_ + gcol] = make_float2(p10, p11);
                *(uint2*)&Ps[r0    *PSTR2 + ck] = make_uint2(f2tf(p00), f2tf(p01));
                *(uint2*)&Ps[(r0+8)*PSTR2 + ck] = make_uint2(f2tf(p10), f2tf(p11));
            }
        }
        cp_wait0();        // V[kt] (and K[kt+1]) landed
        __syncthreads();   // P + V visible to all threads

        // ---- PV (tf32, unchanged): warp 32q x 16d, k-dim = 128 keys ----
        #pragma unroll
        for (int kc = 0; kc < 16; kc++) {
            unsigned a2[2][4];
            ldsm4(a2[0], pbase + (unsigned)(kc*8) * 4u);
            ldsm4(a2[1], pbase + (unsigned)(16*PSTR2 + kc*8) * 4u);
            unsigned vb[2][2];
            #pragma unroll
            for (int f = 0; f < 2; f++) {
                const int d = wn2*16 + f*8 + gr;
                vb[f][0] = Vs[(kc*8 + tg    )*VSTR + d];
                vb[f][1] = Vs[(kc*8 + tg + 4)*VSTR + d];
            }
            #pragma unroll
            for (int mi = 0; mi < 2; mi++)
                #pragma unroll
                for (int f = 0; f < 2; f++)
                    mma_tf32(cacc[mi][f], a2[mi][0], a2[mi][1], a2[mi][2], a2[mi][3],
                             vb[f][0], vb[f][1]);
        }
    }

    // ---- context write (already normalized), permuted to [b][s][h*64+d] ----
    #pragma unroll
    for (int mi = 0; mi < 2; mi++) {
        const int r0 = wm2*32 + mi*16 + gr;
        #pragma unroll
        for (int f = 0; f < 2; f++) {
            const int d = wn2*16 + f*8 + 2*tg;
            size_t d0 = ((size_t)(b*S_ + qt*128 + r0    )) * DM_ + h*DK_ + d;
            size_t d1 = ((size_t)(b*S_ + qt*128 + r0 + 8)) * DM_ + h*DK_ + d;
            *(float2*)&g_Ctx[d0] = make_float2(cacc[mi][f][0], cacc[mi][f][1]);
            *(float2*)&g_Ctx[d1] = make_float2(cacc[mi][f][2], cacc[mi][f][3]);
        }
    }
}

// ---------------------------------------------------------------------------
extern "C" void kernel_launch(void* const* d_in, const int* in_sizes, int n_in,
                              void* d_out, int out_size)
{
    const float* q    = (const float*)d_in[0];
    const float* k    = (const float*)d_in[1];
    const float* v    = (const float*)d_in[2];
    const int*   mask = (const int*)  d_in[3];
    const float* Wq   = (const float*)d_in[4];
    const float* Wk   = (const float*)d_in[5];
    const float* Wv   = (const float*)d_in[6];
    const float* Wo   = (const float*)d_in[7];
    const float* bo   = (const float*)d_in[8];

    float* out      = (float*)d_out;
    float* ctx_out  = out;                             // [B,S,DM]
    float* attn_out = out + (size_t)B_ * S_ * DM_;     // [B,H,S,S]

    void *pQ, *pK, *pV, *pC;
    cudaGetSymbolAddress(&pQ, g_Qh);
    cudaGetSymbolAddress(&pK, g_Kh);
    cudaGetSymbolAddress(&pV, g_Vh);
    cudaGetSymbolAddress(&pC, g_Ctx);

    const int smemAttn = SM_WORDS * 4;   // 160256
    cudaFuncSetAttribute(attn_mma, cudaFuncAttributeMaxDynamicSharedMemorySize, smemAttn);

    // QKV projections in ONE launch (1536 proj blocks, 3 GEMMs by bid>>9)
    // + 2048 mask-pack aux blocks filling the wave tail.
    proj_fused<<<1536 + 2048, 256>>>(q, Wq, (float*)pQ,
                                     k, Wk, (float*)pK,
                                     v, Wv, (float*)pV,
                                     nullptr, 1, 1536, mask);

    attn_mma<<<dim3(S_/128, B_*H_), 512, smemAttn>>>(attn_out);

    // Output projection only — attention is written normalized.
    proj_fused<<<512, 256>>>((const float*)pC, Wo, ctx_out,
                             nullptr, nullptr, nullptr,
                             nullptr, nullptr, nullptr,
                             bo, 0, 512, nullptr);
}

// round 15
// speedup vs baseline: 1.6555x; 1.1350x over previous
#include <cuda_runtime.h>
#include <cuda_fp16.h>

#define B_  4
#define S_  2048
#define DM_ 1024
#define H_  16
#define DK_ 64
#define M_  (B_*S_)   // 8192 rows

// Scratch (allocation-free rule: __device__ globals)
__device__ __half g_Qh[(size_t)B_*H_*S_*DK_];   // fp16, pre-scaled by 1/8
__device__ __half g_Kh[(size_t)B_*H_*S_*DK_];   // fp16
__device__ __half g_Vh[(size_t)B_*H_*S_*DK_];   // fp16
__device__ float  g_Ctx[(size_t)M_*DM_];
__device__ unsigned g_mbits[(size_t)B_*S_*(S_/32)];   // packed mask bits

// ---------------------------------------------------------------------------
// helpers
// ---------------------------------------------------------------------------
__device__ __forceinline__ unsigned f2tf(float x) {
    unsigned u;
    asm("cvt.rna.tf32.f32 %0, %1;" : "=r"(u) : "f"(x));
    return u;
}
__device__ __forceinline__ unsigned pk_h2(float lo, float hi) {
    unsigned u;
    asm("cvt.rn.f16x2.f32 %0, %1, %2;" : "=r"(u) : "f"(hi), "f"(lo));
    return u;
}
__device__ __forceinline__ void mma_tf32(float c[4],
                                         unsigned a0, unsigned a1, unsigned a2, unsigned a3,
                                         unsigned b0, unsigned b1) {
    asm("mma.sync.aligned.m16n8k8.row.col.f32.tf32.tf32.f32 "
        "{%0,%1,%2,%3},{%4,%5,%6,%7},{%8,%9},{%0,%1,%2,%3};"
        : "+f"(c[0]), "+f"(c[1]), "+f"(c[2]), "+f"(c[3])
        : "r"(a0), "r"(a1), "r"(a2), "r"(a3), "r"(b0), "r"(b1));
}
__device__ __forceinline__ void mma_f16(float c[4],
                                        unsigned a0, unsigned a1, unsigned a2, unsigned a3,
                                        unsigned b0, unsigned b1) {
    asm("mma.sync.aligned.m16n8k16.row.col.f32.f16.f16.f32 "
        "{%0,%1,%2,%3},{%4,%5,%6,%7},{%8,%9},{%0,%1,%2,%3};"
        : "+f"(c[0]), "+f"(c[1]), "+f"(c[2]), "+f"(c[3])
        : "r"(a0), "r"(a1), "r"(a2), "r"(a3), "r"(b0), "r"(b1));
}
__device__ __forceinline__ unsigned sm_u32(const void* p) {
    return (unsigned)__cvta_generic_to_shared(p);
}
__device__ __forceinline__ void ldsm4(unsigned r[4], unsigned addr) {
    asm volatile("ldmatrix.sync.aligned.m8n8.x4.shared.b16 {%0,%1,%2,%3}, [%4];"
        : "=r"(r[0]), "=r"(r[1]), "=r"(r[2]), "=r"(r[3]) : "r"(addr));
}
__device__ __forceinline__ void ldsm4t(unsigned r[4], unsigned addr) {
    asm volatile("ldmatrix.sync.aligned.m8n8.x4.trans.shared.b16 {%0,%1,%2,%3}, [%4];"
        : "=r"(r[0]), "=r"(r[1]), "=r"(r[2]), "=r"(r[3]) : "r"(addr));
}
__device__ __forceinline__ void cp16(unsigned dst, const void* src) {
    asm volatile("cp.async.cg.shared.global [%0], [%1], 16;" :: "r"(dst), "l"(src));
}
__device__ __forceinline__ void cp_commit() {
    asm volatile("cp.async.commit_group;");
}
__device__ __forceinline__ void cp_wait0() {
    asm volatile("cp.async.wait_group 0;" ::: "memory");
}

// ---------------------------------------------------------------------------
// Fused projection GEMM (up to 3 GEMMs per launch by bid>>9) + mask-pack aux.
// Proj: 128x128 tile, BK=32, 8 warps 2(m)x4(n), warp 64m x 32n.
// __launch_bounds__(256, 2) pins regs <= 128 (2 CTAs/SM).
// headsMode=1: fp16 outputs (Q scaled 1/8 when which==0; K, V unscaled).
// headsMode=0: flat fp32 + bias.
// ---------------------------------------------------------------------------
#define XSTR 36
__global__ __launch_bounds__(256, 2) void proj_fused(
    const float* __restrict__ X0, const float* __restrict__ W0, float* __restrict__ Y0,
    const float* __restrict__ X1, const float* __restrict__ W1, float* __restrict__ Y1,
    const float* __restrict__ X2, const float* __restrict__ W2, float* __restrict__ Y2,
    const float* __restrict__ bias,
    int headsMode, int nProj,
    const int* __restrict__ mask)
{
    const int bid = blockIdx.x;
    if (bid >= nProj) {                // ---- pack mask bits ----
        const int aux = bid - nProj;
        const int lane = threadIdx.x & 31, w = threadIdx.x >> 5;
        size_t base = (size_t)aux * 256 + (size_t)w * 32;
        #pragma unroll 4
        for (int i = 0; i < 32; i++) {
            int m = mask[(base + i) * 32 + lane];
            unsigned bits = __ballot_sync(0xffffffffu, m != 0);
            if (lane == 0) g_mbits[base + i] = bits;
        }
        return;
    }

    const int which = bid >> 9;        // which GEMM (0..2)
    const int sub = bid & 511;
    const float* X = (which == 0) ? X0 : (which == 1) ? X1 : X2;
    const float* W = (which == 0) ? W0 : (which == 1) ? W1 : W2;
    float*       Y = (which == 0) ? Y0 : (which == 1) ? Y1 : Y2;

    __shared__ unsigned Xs[128 * XSTR];
    __shared__ unsigned Ws[128 * XSTR];
    const int tid = threadIdx.x;
    const int lane = tid & 31, wid = tid >> 5;
    const int wm = wid >> 2, wn = wid & 3;
    const int gr = lane >> 2, tg = lane & 3;
    const int m0 = (sub & 63) * 128, n0 = (sub >> 6) * 128;

    const int arow = lane & 15;
    const int acol = ((lane >> 4) & 1) * 4;
    const int brow = ((lane >> 4) & 1) * 8 + (lane & 7);
    const int bcol = ((lane >> 3) & 1) * 4;
    const unsigned abase = sm_u32(Xs + (wm*64 + arow)*XSTR + acol);
    const unsigned bbase = sm_u32(Ws + (wn*32 + brow)*XSTR + bcol);

    const int lr = tid >> 1;          // 0..127 (row)
    const int lh = (tid & 1) * 16;    // k-half

    float c[4][4][4];
    #pragma unroll
    for (int mi = 0; mi < 4; mi++)
        #pragma unroll
        for (int ni = 0; ni < 4; ni++)
            #pragma unroll
            for (int r = 0; r < 4; r++) c[mi][ni][r] = 0.f;

    const float* Xp = X + (size_t)(m0 + lr) * DM_ + lh;
    const float* Wp = W + (size_t)(n0 + lr) * DM_ + lh;

    float4 px[4], pw[4];
    #pragma unroll
    for (int j = 0; j < 4; j++) { px[j] = *(const float4*)(Xp + 4*j); pw[j] = *(const float4*)(Wp + 4*j); }

    #pragma unroll 1
    for (int it = 0; it < 32; it++) {
        #pragma unroll
        for (int j = 0; j < 4; j++) {
            *(uint4*)&Xs[lr*XSTR + lh + 4*j] = make_uint4(f2tf(px[j].x), f2tf(px[j].y), f2tf(px[j].z), f2tf(px[j].w));
            *(uint4*)&Ws[lr*XSTR + lh + 4*j] = make_uint4(f2tf(pw[j].x), f2tf(pw[j].y), f2tf(pw[j].z), f2tf(pw[j].w));
        }
        __syncthreads();

        if (it + 1 < 32) {
            const int ko = (it + 1) * 32;
            #pragma unroll
            for (int j = 0; j < 4; j++) { px[j] = *(const float4*)(Xp + ko + 4*j); pw[j] = *(const float4*)(Wp + ko + 4*j); }
        }

        #pragma unroll
        for (int kc = 0; kc < 4; kc++) {
            unsigned a[4][4], bb[4][2];
            #pragma unroll
            for (int mi = 0; mi < 4; mi++)
                ldsm4(a[mi], abase + (unsigned)(mi*16*XSTR + kc*8) * 4u);
            #pragma unroll
            for (int np = 0; np < 2; np++) {
                unsigned t[4];
                ldsm4(t, bbase + (unsigned)(np*16*XSTR + kc*8) * 4u);
                bb[2*np][0] = t[0]; bb[2*np][1] = t[1];
                bb[2*np+1][0] = t[2]; bb[2*np+1][1] = t[3];
            }
            #pragma unroll
            for (int mi = 0; mi < 4; mi++)
                #pragma unroll
                for (int ni = 0; ni < 4; ni++)
                    mma_tf32(c[mi][ni], a[mi][0], a[mi][1], a[mi][2], a[mi][3],
                             bb[ni][0], bb[ni][1]);
        }
        __syncthreads();
    }

    if (headsMode) {
        const float s = (which == 0) ? 0.125f : 1.0f;
        #pragma unroll
        for (int mi = 0; mi < 4; mi++) {
            int m = m0 + wm*64 + mi*16 + gr;
            int b = m >> 11, sq = m & (S_ - 1);
            #pragma unroll
            for (int ni = 0; ni < 4; ni++) {
                int n = n0 + wn*32 + ni*8 + 2*tg;
                int h = n >> 6, dk = n & 63;
                size_t base = (((size_t)(b*H_ + h) * S_) + sq) * DK_ + dk;
                __half* Yh = (__half*)Y;
                *(unsigned*)&Yh[base]          = pk_h2(c[mi][ni][0]*s, c[mi][ni][1]*s);
                *(unsigned*)&Yh[base + 8*DK_]  = pk_h2(c[mi][ni][2]*s, c[mi][ni][3]*s);
            }
        }
    } else {
        #pragma unroll
        for (int mi = 0; mi < 4; mi++) {
            int m = m0 + wm*64 + mi*16 + gr;
            #pragma unroll
            for (int ni = 0; ni < 4; ni++) {
                int n = n0 + wn*32 + ni*8 + 2*tg;
                float b0 = bias[n], b1 = bias[n+1];
                *(float2*)&Y[(size_t)m * DM_ + n] =
                    make_float2(c[mi][ni][0] + b0, c[mi][ni][1] + b1);
                *(float2*)&Y[(size_t)(m+8) * DM_ + n] =
                    make_float2(c[mi][ni][2] + b0, c[mi][ni][3] + b1);
            }
        }
    }
}

// ---------------------------------------------------------------------------
// Fused attention, 512 threads / 16 warps, TWO-PASS normalized output.
// Scores: fp16 m16n8k16 (Q,K fp16), warps 4x4, warp 32q x 32k.
// PV:     fp16 m16n8k16 (P fp16 smem via ldsm, V fp16 via ldsm.trans),
//         warps 4x4, warp 32q x 16d, 8 chunks of 16 keys.
// K double-buffered cp.async; V cp.async in pass 2. All fp16 = half traffic.
// smem words: Qs(h) 4608 | Ks(h) 2x4608 | Vs(h) 4608 | Ps(h) 8704 | rowSum 128
// ---------------------------------------------------------------------------
#define QSTRH 36      // words per 64-half row (32 + 4 pad)
#define VSTRH 36
#define PSTRH 68      // words per 128-half row (64 + 4 pad)
#define OFF_KS 4608
#define OFF_VS 13824
#define OFF_PS 18432
#define OFF_RS 27136
#define SM_WORDS 27264
#define KBYTES (4608u * 4u)

__global__ __launch_bounds__(512) void attn_mma(float* __restrict__ attn)
{
    extern __shared__ unsigned smu[];
    unsigned* Qs = smu;            // fp16 [q][d], stride 36 words
    unsigned* Ks = smu + OFF_KS;   // fp16, two buffers of 4608 words
    unsigned* Vs = smu + OFF_VS;   // fp16 [key][d], stride 36 words
    unsigned* Ps = smu + OFF_PS;   // fp16 [q][k], stride 68 words
    float* rowSum = (float*)(smu + OFF_RS);   // later holds 1/l

    const int tid = threadIdx.x;
    const int lane = tid & 31, wid = tid >> 5;
    const int wm = wid >> 2, wn = wid & 3;       // score map: 32q x 32k
    const int wm2 = wid & 3, wn2 = wid >> 2;     // PV map:    32q x 16d
    const int gr = lane >> 2, tg = lane & 3;
    const int qt = blockIdx.x, bh = blockIdx.y;
    const int b = bh >> 4, h = bh & 15;

    // fp16 ldsm addressing
    const unsigned qbase = sm_u32(Qs + (wm*32 + (lane & 15))*QSTRH + ((lane >> 4) & 1)*4);
    const unsigned kbase = sm_u32(Ks + (wn*32 + (lane & 7) + ((lane >> 3) & 1)*8)*QSTRH
                                     + ((lane >> 4) & 1)*4);
    const unsigned pbase = sm_u32(Ps + (wm2*32 + (lane & 15))*PSTRH + ((lane >> 4) & 1)*4);
    // V B-frag (x4.trans): key = ((lane>>3)&1)*8 + (lane&7); d = wn2*16 + (lane>>4)*8
    const unsigned vbase = sm_u32((char*)Vs
        + (size_t)(((lane >> 3) & 1) * 8 + (lane & 7)) * (VSTRH*4)
        + (size_t)(wn2*16 + (lane >> 4) * 8) * 2);

    const __half* Qb = g_Qh + ((size_t)bh * S_ + qt*128) * DK_;
    const __half* Kb = g_Kh + (size_t)bh * S_ * DK_;
    const __half* Vb = g_Vh + (size_t)bh * S_ * DK_;
    const unsigned* mbp = g_mbits + ((size_t)b * S_ + qt*128) * (S_/32);
    float* ab = attn + (size_t)bh * S_ * S_ + (size_t)qt * 128 * S_;

    if (tid < 128) rowSum[tid] = 0.f;

    const int lr = tid >> 2;            // 0..127
    const int segh = (tid & 3) * 16;    // d quarter in halves
    const unsigned qsts = sm_u32(Qs + lr*QSTRH + (segh >> 1));
    const unsigned ksts = sm_u32(Ks + lr*QSTRH + (segh >> 1));
    const unsigned vsts = sm_u32(Vs + lr*VSTRH + (segh >> 1));

    { // prologue: Q tile + K[0] via cp.async (fp16: 2x16B each)
        const __half* qp = Qb + (size_t)lr * DK_ + segh;
        const __half* kp = Kb + (size_t)lr * DK_ + segh;
        cp16(qsts,       qp);
        cp16(qsts + 16u, qp + 8);
        cp16(ksts,       kp);
        cp16(ksts + 16u, kp + 8);
        cp_commit();
        cp_wait0();
    }

    float lacc[4];
    #pragma unroll
    for (int i = 0; i < 4; i++) lacc[i] = 0.f;

    // ================= PASS 1: row sums only =================
    for (int kt = 0; kt < 16; kt++) {
        __syncthreads();
        if (kt + 1 < 16) {
            const __half* kp = Kb + (size_t)((kt+1)*128 + lr) * DK_ + segh;
            const unsigned kdst = ksts + ((kt+1) & 1) * KBYTES;
            cp16(kdst,       kp);
            cp16(kdst + 16u, kp + 8);
            cp_commit();
        }
        unsigned mw[2][2];
        #pragma unroll
        for (int mi = 0; mi < 2; mi++) {
            const int r0 = wm*32 + mi*16 + gr;
            mw[mi][0] = mbp[(size_t)r0      * (S_/32) + kt*4 + wn];
            mw[mi][1] = mbp[(size_t)(r0+8)  * (S_/32) + kt*4 + wn];
        }

        const unsigned kb = kbase + (kt & 1) * KBYTES;
        float sc[2][4][4];
        #pragma unroll
        for (int mi = 0; mi < 2; mi++)
            #pragma unroll
            for (int ni = 0; ni < 4; ni++)
                #pragma unroll
                for (int r = 0; r < 4; r++) sc[mi][ni][r] = 0.f;

        #pragma unroll
        for (int kc = 0; kc < 4; kc++) {          // k16 per step
            unsigned a[2][4], bbf[4][2];
            ldsm4(a[0], qbase + (unsigned)(kc*8) * 4u);
            ldsm4(a[1], qbase + (unsigned)(16*QSTRH + kc*8) * 4u);
            #pragma unroll
            for (int np = 0; np < 2; np++) {
                unsigned t[4];
                ldsm4(t, kb + (unsigned)(np*16*QSTRH + kc*8) * 4u);
                bbf[2*np][0]   = t[0]; bbf[2*np][1]   = t[2];
                bbf[2*np+1][0] = t[1]; bbf[2*np+1][1] = t[3];
            }
            #pragma unroll
            for (int mi = 0; mi < 2; mi++)
                #pragma unroll
                for (int ni = 0; ni < 4; ni++)
                    mma_f16(sc[mi][ni], a[mi][0], a[mi][1], a[mi][2], a[mi][3],
                            bbf[ni][0], bbf[ni][1]);
        }

        #pragma unroll
        for (int mi = 0; mi < 2; mi++) {
            #pragma unroll
            for (int ni = 0; ni < 4; ni++) {
                const int bit = ni*8 + 2*tg;
                float p00 = (mw[mi][0] >> bit     & 1u) ? __expf(sc[mi][ni][0]) : 0.f;
                float p01 = (mw[mi][0] >> (bit+1) & 1u) ? __expf(sc[mi][ni][1]) : 0.f;
                float p10 = (mw[mi][1] >> bit     & 1u) ? __expf(sc[mi][ni][2]) : 0.f;
                float p11 = (mw[mi][1] >> (bit+1) & 1u) ? __expf(sc[mi][ni][3]) : 0.f;
                lacc[mi*2]   += p00 + p01;
                lacc[mi*2+1] += p10 + p11;
            }
        }
        cp_wait0();        // K[kt+1] landed, overlapped with scores+exp
    }

    // ---- reduce row sums; rowSum becomes 1/l ----
    #pragma unroll
    for (int i = 0; i < 4; i++) {
        float v = lacc[i];
        v += __shfl_xor_sync(0xffffffffu, v, 1);
        v += __shfl_xor_sync(0xffffffffu, v, 2);
        lacc[i] = v;
    }
    if (tg == 0) {
        #pragma unroll
        for (int mi = 0; mi < 2; mi++) {
            atomicAdd(&rowSum[wm*32 + mi*16 + gr],     lacc[mi*2]);
            atomicAdd(&rowSum[wm*32 + mi*16 + gr + 8], lacc[mi*2+1]);
        }
    }
    __syncthreads();
    if (tid < 128) rowSum[tid] = 1.0f / rowSum[tid];
    __syncthreads();

    float inv0[2], inv1[2];
    #pragma unroll
    for (int mi = 0; mi < 2; mi++) {
        inv0[mi] = rowSum[wm*32 + mi*16 + gr];
        inv1[mi] = rowSum[wm*32 + mi*16 + gr + 8];
    }

    { // pass-2 prologue: K[0] into buffer 0
        const __half* kp = Kb + (size_t)lr * DK_ + segh;
        cp16(ksts,       kp);
        cp16(ksts + 16u, kp + 8);
        cp_commit();
        cp_wait0();
    }

    float cacc[2][2][4];
    #pragma unroll
    for (int mi = 0; mi < 2; mi++)
        #pragma unroll
        for (int f = 0; f < 2; f++)
            #pragma unroll
            for (int r = 0; r < 4; r++) cacc[mi][f][r] = 0.f;

    // ================= PASS 2: normalized probs + PV =================
    for (int kt = 0; kt < 16; kt++) {
        __syncthreads();   // prev PV done with Vs/Ps; K[kt] visible
        {
            const __half* vp = Vb + (size_t)(kt*128 + lr) * DK_ + segh;
            cp16(vsts,       vp);
            cp16(vsts + 16u, vp + 8);
            if (kt + 1 < 16) {
                const __half* kp = Kb + (size_t)((kt+1)*128 + lr) * DK_ + segh;
                const unsigned kdst = ksts + ((kt+1) & 1) * KBYTES;
                cp16(kdst,       kp);
                cp16(kdst + 16u, kp + 8);
            }
            cp_commit();
        }
        unsigned mw[2][2];
        #pragma unroll
        for (int mi = 0; mi < 2; mi++) {
            const int r0 = wm*32 + mi*16 + gr;
            mw[mi][0] = mbp[(size_t)r0      * (S_/32) + kt*4 + wn];
            mw[mi][1] = mbp[(size_t)(r0+8)  * (S_/32) + kt*4 + wn];
        }

        const unsigned kb = kbase + (kt & 1) * KBYTES;
        float sc[2][4][4];
        #pragma unroll
        for (int mi = 0; mi < 2; mi++)
            #pragma unroll
            for (int ni = 0; ni < 4; ni++)
                #pragma unroll
                for (int r = 0; r < 4; r++) sc[mi][ni][r] = 0.f;

        #pragma unroll
        for (int kc = 0; kc < 4; kc++) {
            unsigned a[2][4], bbf[4][2];
            ldsm4(a[0], qbase + (unsigned)(kc*8) * 4u);
            ldsm4(a[1], qbase + (unsigned)(16*QSTRH + kc*8) * 4u);
            #pragma unroll
            for (int np = 0; np < 2; np++) {
                unsigned t[4];
                ldsm4(t, kb + (unsigned)(np*16*QSTRH + kc*8) * 4u);
                bbf[2*np][0]   = t[0]; bbf[2*np][1]   = t[2];
                bbf[2*np+1][0] = t[1]; bbf[2*np+1][1] = t[3];
            }
            #pragma unroll
            for (int mi = 0; mi < 2; mi++)
                #pragma unroll
                for (int ni = 0; ni < 4; ni++)
                    mma_f16(sc[mi][ni], a[mi][0], a[mi][1], a[mi][2], a[mi][3],
                            bbf[ni][0], bbf[ni][1]);
        }

        // mask + exp, normalized; write final probs (fp32) + Ps (fp16)
        #pragma unroll
        for (int mi = 0; mi < 2; mi++) {
            const int r0 = wm*32 + mi*16 + gr;
            #pragma unroll
            for (int ni = 0; ni < 4; ni++) {
                const int ck = wn*32 + ni*8 + 2*tg;
                const int bit = ni*8 + 2*tg;
                const size_t gcol = (size_t)kt*128 + ck;
                float p00 = (mw[mi][0] >> bit     & 1u) ? __expf(sc[mi][ni][0]) * inv0[mi] : 0.f;
                float p01 = (mw[mi][0] >> (bit+1) & 1u) ? __expf(sc[mi][ni][1]) * inv0[mi] : 0.f;
                float p10 = (mw[mi][1] >> bit     & 1u) ? __expf(sc[mi][ni][2]) * inv1[mi] : 0.f;
                float p11 = (mw[mi][1] >> (bit+1) & 1u) ? __expf(sc[mi][ni][3]) * inv1[mi] : 0.f;
                *(float2*)&ab[(size_t)r0     * S_ + gcol] = make_float2(p00, p01);
                *(float2*)&ab[(size_t)(r0+8) * S_ + gcol] = make_float2(p10, p11);
                Ps[r0    *PSTRH + (ck >> 1)] = pk_h2(p00, p01);
                Ps[(r0+8)*PSTRH + (ck >> 1)] = pk_h2(p10, p11);
            }
        }
        cp_wait0();        // V[kt] (and K[kt+1]) landed
        __syncthreads();   // P + V visible to all threads

        // ---- PV (fp16 m16n8k16): warp 32q x 16d, 8 chunks of 16 keys ----
        #pragma unroll
        for (int kc = 0; kc < 8; kc++) {
            unsigned a2[2][4];
            ldsm4(a2[0], pbase + (unsigned)(kc*8) * 4u);
            ldsm4(a2[1], pbase + (unsigned)(16*PSTRH + kc*8) * 4u);
            unsigned vbf[4];
            ldsm4t(vbf, vbase + (unsigned)(kc*16*VSTRH) * 4u);
            #pragma unroll
            for (int mi = 0; mi < 2; mi++) {
                mma_f16(cacc[mi][0], a2[mi][0], a2[mi][1], a2[mi][2], a2[mi][3],
                        vbf[0], vbf[1]);
                mma_f16(cacc[mi][1], a2[mi][0], a2[mi][1], a2[mi][2], a2[mi][3],
                        vbf[2], vbf[3]);
            }
        }
    }

    // ---- context write (already normalized), permuted to [b][s][h*64+d] ----
    #pragma unroll
    for (int mi = 0; mi < 2; mi++) {
        const int r0 = wm2*32 + mi*16 + gr;
        #pragma unroll
        for (int f = 0; f < 2; f++) {
            const int d = wn2*16 + f*8 + 2*tg;
            size_t d0 = ((size_t)(b*S_ + qt*128 + r0    )) * DM_ + h*DK_ + d;
            size_t d1 = ((size_t)(b*S_ + qt*128 + r0 + 8)) * DM_ + h*DK_ + d;
            *(float2*)&g_Ctx[d0] = make_float2(cacc[mi][f][0], cacc[mi][f][1]);
            *(float2*)&g_Ctx[d1] = make_float2(cacc[mi][f][2], cacc[mi][f][3]);
        }
    }
}

// ---------------------------------------------------------------------------
extern "C" void kernel_launch(void* const* d_in, const int* in_sizes, int n_in,
                              void* d_out, int out_size)
{
    const float* q    = (const float*)d_in[0];
    const float* k    = (const float*)d_in[1];
    const float* v    = (const float*)d_in[2];
    const int*   mask = (const int*)  d_in[3];
    const float* Wq   = (const float*)d_in[4];
    const float* Wk   = (const float*)d_in[5];
    const float* Wv   = (const float*)d_in[6];
    const float* Wo   = (const float*)d_in[7];
    const float* bo   = (const float*)d_in[8];

    float* out      = (float*)d_out;
    float* ctx_out  = out;                             // [B,S,DM]
    float* attn_out = out + (size_t)B_ * S_ * DM_;     // [B,H,S,S]

    void *pQ, *pK, *pV, *pC;
    cudaGetSymbolAddress(&pQ, g_Qh);
    cudaGetSymbolAddress(&pK, g_Kh);
    cudaGetSymbolAddress(&pV, g_Vh);
    cudaGetSymbolAddress(&pC, g_Ctx);

    const int smemAttn = SM_WORDS * 4;   // 109056
    cudaFuncSetAttribute(attn_mma, cudaFuncAttributeMaxDynamicSharedMemorySize, smemAttn);

    // QKV projections in ONE launch (1536 proj blocks, 3 GEMMs by bid>>9)
    // + 2048 mask-pack aux blocks filling the wave tail.
    proj_fused<<<1536 + 2048, 256>>>(q, Wq, (float*)pQ,
                                     k, Wk, (float*)pK,
                                     v, Wv, (float*)pV,
                                     nullptr, 1, 1536, mask);

    attn_mma<<<dim3(S_/128, B_*H_), 512, smemAttn>>>(attn_out);

    // Output projection only — attention is written normalized.
    proj_fused<<<512, 256>>>((const float*)pC, Wo, ctx_out,
                             nullptr, nullptr, nullptr,
                             nullptr, nullptr, nullptr,
                             bo, 0, 512, nullptr);
}

// round 16
// speedup vs baseline: 1.8273x; 1.1038x over previous
#include <cuda_runtime.h>
#include <cuda_fp16.h>

#define B_  4
#define S_  2048
#define DM_ 1024
#define H_  16
#define DK_ 64
#define M_  (B_*S_)   // 8192 rows

// Scratch (allocation-free rule: __device__ globals)
__device__ __half g_Qh[(size_t)B_*H_*S_*DK_];   // fp16, pre-scaled by 1/8
__device__ __half g_Kh[(size_t)B_*H_*S_*DK_];   // fp16
__device__ __half g_Vh[(size_t)B_*H_*S_*DK_];   // fp16
__device__ float  g_Ctx[(size_t)M_*DM_];
__device__ unsigned g_mbits[(size_t)B_*S_*(S_/32)];   // packed mask bits

// ---------------------------------------------------------------------------
// helpers
// ---------------------------------------------------------------------------
__device__ __forceinline__ unsigned pk_h2(float lo, float hi) {
    unsigned u;
    asm("cvt.rn.f16x2.f32 %0, %1, %2;" : "=r"(u) : "f"(hi), "f"(lo));
    return u;
}
__device__ __forceinline__ void mma_f16(float c[4],
                                        unsigned a0, unsigned a1, unsigned a2, unsigned a3,
                                        unsigned b0, unsigned b1) {
    asm("mma.sync.aligned.m16n8k16.row.col.f32.f16.f16.f32 "
        "{%0,%1,%2,%3},{%4,%5,%6,%7},{%8,%9},{%0,%1,%2,%3};"
        : "+f"(c[0]), "+f"(c[1]), "+f"(c[2]), "+f"(c[3])
        : "r"(a0), "r"(a1), "r"(a2), "r"(a3), "r"(b0), "r"(b1));
}
__device__ __forceinline__ unsigned sm_u32(const void* p) {
    return (unsigned)__cvta_generic_to_shared(p);
}
__device__ __forceinline__ void ldsm4(unsigned r[4], unsigned addr) {
    asm volatile("ldmatrix.sync.aligned.m8n8.x4.shared.b16 {%0,%1,%2,%3}, [%4];"
        : "=r"(r[0]), "=r"(r[1]), "=r"(r[2]), "=r"(r[3]) : "r"(addr));
}
__device__ __forceinline__ void ldsm4t(unsigned r[4], unsigned addr) {
    asm volatile("ldmatrix.sync.aligned.m8n8.x4.trans.shared.b16 {%0,%1,%2,%3}, [%4];"
        : "=r"(r[0]), "=r"(r[1]), "=r"(r[2]), "=r"(r[3]) : "r"(addr));
}
__device__ __forceinline__ void cp16(unsigned dst, const void* src) {
    asm volatile("cp.async.cg.shared.global [%0], [%1], 16;" :: "r"(dst), "l"(src));
}
__device__ __forceinline__ void cp_commit() {
    asm volatile("cp.async.commit_group;");
}
__device__ __forceinline__ void cp_wait0() {
    asm volatile("cp.async.wait_group 0;" ::: "memory");
}

// ---------------------------------------------------------------------------
// Fused projection GEMM, fp16 m16n8k16 (fp32 accumulate).
// Up to 3 GEMMs per launch by bid>>9 + mask-pack aux blocks >= nProj.
// Tile 128x128, BK=32, 8 warps 2(m)x4(n), warp 64m x 32n.
// Per BK-iter: 2 k16 chunks, each 6 ldsm4 + 16 mma_f16.
// __launch_bounds__(256, 2) pins regs <= 128 (2 CTAs/SM).
// ---------------------------------------------------------------------------
#define XSTRH 20   // words per 32-half row (16 + 4 pad) -> conflict-free ldsm
__global__ __launch_bounds__(256, 2) void proj_fused(
    const float* __restrict__ X0, const float* __restrict__ W0, float* __restrict__ Y0,
    const float* __restrict__ X1, const float* __restrict__ W1, float* __restrict__ Y1,
    const float* __restrict__ X2, const float* __restrict__ W2, float* __restrict__ Y2,
    const float* __restrict__ bias,
    int headsMode, int nProj,
    const int* __restrict__ mask)
{
    const int bid = blockIdx.x;
    if (bid >= nProj) {                // ---- pack mask bits ----
        const int aux = bid - nProj;
        const int lane = threadIdx.x & 31, w = threadIdx.x >> 5;
        size_t base = (size_t)aux * 256 + (size_t)w * 32;
        #pragma unroll 4
        for (int i = 0; i < 32; i++) {
            int m = mask[(base + i) * 32 + lane];
            unsigned bits = __ballot_sync(0xffffffffu, m != 0);
            if (lane == 0) g_mbits[base + i] = bits;
        }
        return;
    }

    const int which = bid >> 9;        // which GEMM (0..2)
    const int sub = bid & 511;
    const float* X = (which == 0) ? X0 : (which == 1) ? X1 : X2;
    const float* W = (which == 0) ? W0 : (which == 1) ? W1 : W2;
    float*       Y = (which == 0) ? Y0 : (which == 1) ? Y1 : Y2;

    __shared__ unsigned Xs[128 * XSTRH];
    __shared__ unsigned Ws[128 * XSTRH];
    const int tid = threadIdx.x;
    const int lane = tid & 31, wid = tid >> 5;
    const int wm = wid >> 2, wn = wid & 3;
    const int gr = lane >> 2, tg = lane & 3;
    const int m0 = (sub & 63) * 128, n0 = (sub >> 6) * 128;

    const unsigned abase = sm_u32(Xs + (wm*64 + (lane & 15))*XSTRH + ((lane >> 4) & 1)*4);
    const unsigned bbase = sm_u32(Ws + (wn*32 + (lane & 7) + ((lane >> 3) & 1)*8)*XSTRH
                                     + ((lane >> 4) & 1)*4);

    const int lr = tid >> 1;          // 0..127 (row)
    const int lh = (tid & 1) * 16;    // k-half (floats)
    const int sts = lr * XSTRH + (tid & 1) * 8;   // word offset (8 words = 16 halves)

    float c[4][4][4];
    #pragma unroll
    for (int mi = 0; mi < 4; mi++)
        #pragma unroll
        for (int ni = 0; ni < 4; ni++)
            #pragma unroll
            for (int r = 0; r < 4; r++) c[mi][ni][r] = 0.f;

    const float* Xp = X + (size_t)(m0 + lr) * DM_ + lh;
    const float* Wp = W + (size_t)(n0 + lr) * DM_ + lh;

    float4 px[4], pw[4];
    #pragma unroll
    for (int j = 0; j < 4; j++) { px[j] = *(const float4*)(Xp + 4*j); pw[j] = *(const float4*)(Wp + 4*j); }

    #pragma unroll 1
    for (int it = 0; it < 32; it++) {
        { // fp16 pack + store: 16 floats -> 8 words per matrix
            uint4 ux0 = make_uint4(pk_h2(px[0].x, px[0].y), pk_h2(px[0].z, px[0].w),
                                   pk_h2(px[1].x, px[1].y), pk_h2(px[1].z, px[1].w));
            uint4 ux1 = make_uint4(pk_h2(px[2].x, px[2].y), pk_h2(px[2].z, px[2].w),
                                   pk_h2(px[3].x, px[3].y), pk_h2(px[3].z, px[3].w));
            uint4 uw0 = make_uint4(pk_h2(pw[0].x, pw[0].y), pk_h2(pw[0].z, pw[0].w),
                                   pk_h2(pw[1].x, pw[1].y), pk_h2(pw[1].z, pw[1].w));
            uint4 uw1 = make_uint4(pk_h2(pw[2].x, pw[2].y), pk_h2(pw[2].z, pw[2].w),
                                   pk_h2(pw[3].x, pw[3].y), pk_h2(pw[3].z, pw[3].w));
            *(uint4*)&Xs[sts]     = ux0;
            *(uint4*)&Xs[sts + 4] = ux1;
            *(uint4*)&Ws[sts]     = uw0;
            *(uint4*)&Ws[sts + 4] = uw1;
        }
        __syncthreads();

        if (it + 1 < 32) {
            const int ko = (it + 1) * 32;
            #pragma unroll
            for (int j = 0; j < 4; j++) { px[j] = *(const float4*)(Xp + ko + 4*j); pw[j] = *(const float4*)(Wp + ko + 4*j); }
        }

        #pragma unroll
        for (int kc = 0; kc < 2; kc++) {           // two k16 chunks
            unsigned a[4][4], bbf[4][2];
            #pragma unroll
            for (int mi = 0; mi < 4; mi++)
                ldsm4(a[mi], abase + (unsigned)(mi*16*XSTRH + kc*8) * 4u);
            #pragma unroll
            for (int np = 0; np < 2; np++) {
                unsigned t[4];
                ldsm4(t, bbase + (unsigned)(np*16*XSTRH + kc*8) * 4u);
                bbf[2*np][0]   = t[0]; bbf[2*np][1]   = t[2];
                bbf[2*np+1][0] = t[1]; bbf[2*np+1][1] = t[3];
            }
            #pragma unroll
            for (int mi = 0; mi < 4; mi++)
                #pragma unroll
                for (int ni = 0; ni < 4; ni++)
                    mma_f16(c[mi][ni], a[mi][0], a[mi][1], a[mi][2], a[mi][3],
                            bbf[ni][0], bbf[ni][1]);
        }
        __syncthreads();
    }

    if (headsMode) {
        const float s = (which == 0) ? 0.125f : 1.0f;
        #pragma unroll
        for (int mi = 0; mi < 4; mi++) {
            int m = m0 + wm*64 + mi*16 + gr;
            int b = m >> 11, sq = m & (S_ - 1);
            #pragma unroll
            for (int ni = 0; ni < 4; ni++) {
                int n = n0 + wn*32 + ni*8 + 2*tg;
                int h = n >> 6, dk = n & 63;
                size_t base = (((size_t)(b*H_ + h) * S_) + sq) * DK_ + dk;
                __half* Yh = (__half*)Y;
                *(unsigned*)&Yh[base]          = pk_h2(c[mi][ni][0]*s, c[mi][ni][1]*s);
                *(unsigned*)&Yh[base + 8*DK_]  = pk_h2(c[mi][ni][2]*s, c[mi][ni][3]*s);
            }
        }
    } else {
        #pragma unroll
        for (int mi = 0; mi < 4; mi++) {
            int m = m0 + wm*64 + mi*16 + gr;
            #pragma unroll
            for (int ni = 0; ni < 4; ni++) {
                int n = n0 + wn*32 + ni*8 + 2*tg;
                float b0 = bias[n], b1 = bias[n+1];
                *(float2*)&Y[(size_t)m * DM_ + n] =
                    make_float2(c[mi][ni][0] + b0, c[mi][ni][1] + b1);
                *(float2*)&Y[(size_t)(m+8) * DM_ + n] =
                    make_float2(c[mi][ni][2] + b0, c[mi][ni][3] + b1);
            }
        }
    }
}

// ---------------------------------------------------------------------------
// Fused attention, 512 threads / 16 warps, TWO-PASS normalized output.
// Scores: fp16 m16n8k16 (Q,K fp16), warps 4x4, warp 32q x 32k.
// PV:     fp16 m16n8k16 (P fp16 smem via ldsm, V fp16 via ldsm.trans),
//         warps 4x4, warp 32q x 16d, 8 chunks of 16 keys.
// K double-buffered cp.async; V cp.async in pass 2. (unchanged from R15)
// smem words: Qs(h) 4608 | Ks(h) 2x4608 | Vs(h) 4608 | Ps(h) 8704 | rowSum 128
// ---------------------------------------------------------------------------
#define QSTRH 36      // words per 64-half row (32 + 4 pad)
#define VSTRH 36
#define PSTRH 68      // words per 128-half row (64 + 4 pad)
#define OFF_KS 4608
#define OFF_VS 13824
#define OFF_PS 18432
#define OFF_RS 27136
#define SM_WORDS 27264
#define KBYTES (4608u * 4u)

__global__ __launch_bounds__(512) void attn_mma(float* __restrict__ attn)
{
    extern __shared__ unsigned smu[];
    unsigned* Qs = smu;            // fp16 [q][d], stride 36 words
    unsigned* Ks = smu + OFF_KS;   // fp16, two buffers of 4608 words
    unsigned* Vs = smu + OFF_VS;   // fp16 [key][d], stride 36 words
    unsigned* Ps = smu + OFF_PS;   // fp16 [q][k], stride 68 words
    float* rowSum = (float*)(smu + OFF_RS);   // later holds 1/l

    const int tid = threadIdx.x;
    const int lane = tid & 31, wid = tid >> 5;
    const int wm = wid >> 2, wn = wid & 3;       // score map: 32q x 32k
    const int wm2 = wid & 3, wn2 = wid >> 2;     // PV map:    32q x 16d
    const int gr = lane >> 2, tg = lane & 3;
    const int qt = blockIdx.x, bh = blockIdx.y;
    const int b = bh >> 4, h = bh & 15;

    const unsigned qbase = sm_u32(Qs + (wm*32 + (lane & 15))*QSTRH + ((lane >> 4) & 1)*4);
    const unsigned kbase = sm_u32(Ks + (wn*32 + (lane & 7) + ((lane >> 3) & 1)*8)*QSTRH
                                     + ((lane >> 4) & 1)*4);
    const unsigned pbase = sm_u32(Ps + (wm2*32 + (lane & 15))*PSTRH + ((lane >> 4) & 1)*4);
    const unsigned vbase = sm_u32((char*)Vs
        + (size_t)(((lane >> 3) & 1) * 8 + (lane & 7)) * (VSTRH*4)
        + (size_t)(wn2*16 + (lane >> 4) * 8) * 2);

    const __half* Qb = g_Qh + ((size_t)bh * S_ + qt*128) * DK_;
    const __half* Kb = g_Kh + (size_t)bh * S_ * DK_;
    const __half* Vb = g_Vh + (size_t)bh * S_ * DK_;
    const unsigned* mbp = g_mbits + ((size_t)b * S_ + qt*128) * (S_/32);
    float* ab = attn + (size_t)bh * S_ * S_ + (size_t)qt * 128 * S_;

    if (tid < 128) rowSum[tid] = 0.f;

    const int lr = tid >> 2;            // 0..127
    const int segh = (tid & 3) * 16;    // d quarter in halves
    const unsigned qsts = sm_u32(Qs + lr*QSTRH + (segh >> 1));
    const unsigned ksts = sm_u32(Ks + lr*QSTRH + (segh >> 1));
    const unsigned vsts = sm_u32(Vs + lr*VSTRH + (segh >> 1));

    { // prologue: Q tile + K[0] via cp.async (fp16: 2x16B each)
        const __half* qp = Qb + (size_t)lr * DK_ + segh;
        const __half* kp = Kb + (size_t)lr * DK_ + segh;
        cp16(qsts,       qp);
        cp16(qsts + 16u, qp + 8);
        cp16(ksts,       kp);
        cp16(ksts + 16u, kp + 8);
        cp_commit();
        cp_wait0();
    }

    float lacc[4];
    #pragma unroll
    for (int i = 0; i < 4; i++) lacc[i] = 0.f;

    // ================= PASS 1: row sums only =================
    for (int kt = 0; kt < 16; kt++) {
        __syncthreads();
        if (kt + 1 < 16) {
            const __half* kp = Kb + (size_t)((kt+1)*128 + lr) * DK_ + segh;
            const unsigned kdst = ksts + ((kt+1) & 1) * KBYTES;
            cp16(kdst,       kp);
            cp16(kdst + 16u, kp + 8);
            cp_commit();
        }
        unsigned mw[2][2];
        #pragma unroll
        for (int mi = 0; mi < 2; mi++) {
            const int r0 = wm*32 + mi*16 + gr;
            mw[mi][0] = mbp[(size_t)r0      * (S_/32) + kt*4 + wn];
            mw[mi][1] = mbp[(size_t)(r0+8)  * (S_/32) + kt*4 + wn];
        }

        const unsigned kb = kbase + (kt & 1) * KBYTES;
        float sc[2][4][4];
        #pragma unroll
        for (int mi = 0; mi < 2; mi++)
            #pragma unroll
            for (int ni = 0; ni < 4; ni++)
                #pragma unroll
                for (int r = 0; r < 4; r++) sc[mi][ni][r] = 0.f;

        #pragma unroll
        for (int kc = 0; kc < 4; kc++) {          // k16 per step
            unsigned a[2][4], bbf[4][2];
            ldsm4(a[0], qbase + (unsigned)(kc*8) * 4u);
            ldsm4(a[1], qbase + (unsigned)(16*QSTRH + kc*8) * 4u);
            #pragma unroll
            for (int np = 0; np < 2; np++) {
                unsigned t[4];
                ldsm4(t, kb + (unsigned)(np*16*QSTRH + kc*8) * 4u);
                bbf[2*np][0]   = t[0]; bbf[2*np][1]   = t[2];
                bbf[2*np+1][0] = t[1]; bbf[2*np+1][1] = t[3];
            }
            #pragma unroll
            for (int mi = 0; mi < 2; mi++)
                #pragma unroll
                for (int ni = 0; ni < 4; ni++)
                    mma_f16(sc[mi][ni], a[mi][0], a[mi][1], a[mi][2], a[mi][3],
                            bbf[ni][0], bbf[ni][1]);
        }

        #pragma unroll
        for (int mi = 0; mi < 2; mi++) {
            #pragma unroll
            for (int ni = 0; ni < 4; ni++) {
                const int bit = ni*8 + 2*tg;
                float p00 = (mw[mi][0] >> bit     & 1u) ? __expf(sc[mi][ni][0]) : 0.f;
                float p01 = (mw[mi][0] >> (bit+1) & 1u) ? __expf(sc[mi][ni][1]) : 0.f;
                float p10 = (mw[mi][1] >> bit     & 1u) ? __expf(sc[mi][ni][2]) : 0.f;
                float p11 = (mw[mi][1] >> (bit+1) & 1u) ? __expf(sc[mi][ni][3]) : 0.f;
                lacc[mi*2]   += p00 + p01;
                lacc[mi*2+1] += p10 + p11;
            }
        }
        cp_wait0();        // K[kt+1] landed, overlapped with scores+exp
    }

    // ---- reduce row sums; rowSum becomes 1/l ----
    #pragma unroll
    for (int i = 0; i < 4; i++) {
        float v = lacc[i];
        v += __shfl_xor_sync(0xffffffffu, v, 1);
        v += __shfl_xor_sync(0xffffffffu, v, 2);
        lacc[i] = v;
    }
    if (tg == 0) {
        #pragma unroll
        for (int mi = 0; mi < 2; mi++) {
            atomicAdd(&rowSum[wm*32 + mi*16 + gr],     lacc[mi*2]);
            atomicAdd(&rowSum[wm*32 + mi*16 + gr + 8], lacc[mi*2+1]);
        }
    }
    __syncthreads();
    if (tid < 128) rowSum[tid] = 1.0f / rowSum[tid];
    __syncthreads();

    float inv0[2], inv1[2];
    #pragma unroll
    for (int mi = 0; mi < 2; mi++) {
        inv0[mi] = rowSum[wm*32 + mi*16 + gr];
        inv1[mi] = rowSum[wm*32 + mi*16 + gr + 8];
    }

    { // pass-2 prologue: K[0] into buffer 0
        const __half* kp = Kb + (size_t)lr * DK_ + segh;
        cp16(ksts,       kp);
        cp16(ksts + 16u, kp + 8);
        cp_commit();
        cp_wait0();
    }

    float cacc[2][2][4];
    #pragma unroll
    for (int mi = 0; mi < 2; mi++)
        #pragma unroll
        for (int f = 0; f < 2; f++)
            #pragma unroll
            for (int r = 0; r < 4; r++) cacc[mi][f][r] = 0.f;

    // ================= PASS 2: normalized probs + PV =================
    for (int kt = 0; kt < 16; kt++) {
        __syncthreads();   // prev PV done with Vs/Ps; K[kt] visible
        {
            const __half* vp = Vb + (size_t)(kt*128 + lr) * DK_ + segh;
            cp16(vsts,       vp);
            cp16(vsts + 16u, vp + 8);
            if (kt + 1 < 16) {
                const __half* kp = Kb + (size_t)((kt+1)*128 + lr) * DK_ + segh;
                const unsigned kdst = ksts + ((kt+1) & 1) * KBYTES;
                cp16(kdst,       kp);
                cp16(kdst + 16u, kp + 8);
            }
            cp_commit();
        }
        unsigned mw[2][2];
        #pragma unroll
        for (int mi = 0; mi < 2; mi++) {
            const int r0 = wm*32 + mi*16 + gr;
            mw[mi][0] = mbp[(size_t)r0      * (S_/32) + kt*4 + wn];
            mw[mi][1] = mbp[(size_t)(r0+8)  * (S_/32) + kt*4 + wn];
        }

        const unsigned kb = kbase + (kt & 1) * KBYTES;
        float sc[2][4][4];
        #pragma unroll
        for (int mi = 0; mi < 2; mi++)
            #pragma unroll
            for (int ni = 0; ni < 4; ni++)
                #pragma unroll
                for (int r = 0; r < 4; r++) sc[mi][ni][r] = 0.f;

        #pragma unroll
        for (int kc = 0; kc < 4; kc++) {
            unsigned a[2][4], bbf[4][2];
            ldsm4(a[0], qbase + (unsigned)(kc*8) * 4u);
            ldsm4(a[1], qbase + (unsigned)(16*QSTRH + kc*8) * 4u);
            #pragma unroll
            for (int np = 0; np < 2; np++) {
                unsigned t[4];
                ldsm4(t, kb + (unsigned)(np*16*QSTRH + kc*8) * 4u);
                bbf[2*np][0]   = t[0]; bbf[2*np][1]   = t[2];
                bbf[2*np+1][0] = t[1]; bbf[2*np+1][1] = t[3];
            }
            #pragma unroll
            for (int mi = 0; mi < 2; mi++)
                #pragma unroll
                for (int ni = 0; ni < 4; ni++)
                    mma_f16(sc[mi][ni], a[mi][0], a[mi][1], a[mi][2], a[mi][3],
                            bbf[ni][0], bbf[ni][1]);
        }

        // mask + exp, normalized; write final probs (fp32) + Ps (fp16)
        #pragma unroll
        for (int mi = 0; mi < 2; mi++) {
            const int r0 = wm*32 + mi*16 + gr;
            #pragma unroll
            for (int ni = 0; ni < 4; ni++) {
                const int ck = wn*32 + ni*8 + 2*tg;
                const int bit = ni*8 + 2*tg;
                const size_t gcol = (size_t)kt*128 + ck;
                float p00 = (mw[mi][0] >> bit     & 1u) ? __expf(sc[mi][ni][0]) * inv0[mi] : 0.f;
                float p01 = (mw[mi][0] >> (bit+1) & 1u) ? __expf(sc[mi][ni][1]) * inv0[mi] : 0.f;
                float p10 = (mw[mi][1] >> bit     & 1u) ? __expf(sc[mi][ni][2]) * inv1[mi] : 0.f;
                float p11 = (mw[mi][1] >> (bit+1) & 1u) ? __expf(sc[mi][ni][3]) * inv1[mi] : 0.f;
                *(float2*)&ab[(size_t)r0     * S_ + gcol] = make_float2(p00, p01);
                *(float2*)&ab[(size_t)(r0+8) * S_ + gcol] = make_float2(p10, p11);
                Ps[r0    *PSTRH + (ck >> 1)] = pk_h2(p00, p01);
                Ps[(r0+8)*PSTRH + (ck >> 1)] = pk_h2(p10, p11);
            }
        }
        cp_wait0();        // V[kt] (and K[kt+1]) landed
        __syncthreads();   // P + V visible to all threads

        // ---- PV (fp16 m16n8k16): warp 32q x 16d, 8 chunks of 16 keys ----
        #pragma unroll
        for (int kc = 0; kc < 8; kc++) {
            unsigned a2[2][4];
            ldsm4(a2[0], pbase + (unsigned)(kc*8) * 4u);
            ldsm4(a2[1], pbase + (unsigned)(16*PSTRH + kc*8) * 4u);
            unsigned vbf[4];
            ldsm4t(vbf, vbase + (unsigned)(kc*16*VSTRH) * 4u);
            #pragma unroll
            for (int mi = 0; mi < 2; mi++) {
                mma_f16(cacc[mi][0], a2[mi][0], a2[mi][1], a2[mi][2], a2[mi][3],
                        vbf[0], vbf[1]);
                mma_f16(cacc[mi][1], a2[mi][0], a2[mi][1], a2[mi][2], a2[mi][3],
                        vbf[2], vbf[3]);
            }
        }
    }

    // ---- context write (already normalized), permuted to [b][s][h*64+d] ----
    #pragma unroll
    for (int mi = 0; mi < 2; mi++) {
        const int r0 = wm2*32 + mi*16 + gr;
        #pragma unroll
        for (int f = 0; f < 2; f++) {
            const int d = wn2*16 + f*8 + 2*tg;
            size_t d0 = ((size_t)(b*S_ + qt*128 + r0    )) * DM_ + h*DK_ + d;
            size_t d1 = ((size_t)(b*S_ + qt*128 + r0 + 8)) * DM_ + h*DK_ + d;
            *(float2*)&g_Ctx[d0] = make_float2(cacc[mi][f][0], cacc[mi][f][1]);
            *(float2*)&g_Ctx[d1] = make_float2(cacc[mi][f][2], cacc[mi][f][3]);
        }
    }
}

// ---------------------------------------------------------------------------
extern "C" void kernel_launch(void* const* d_in, const int* in_sizes, int n_in,
                              void* d_out, int out_size)
{
    const float* q    = (const float*)d_in[0];
    const float* k    = (const float*)d_in[1];
    const float* v    = (const float*)d_in[2];
    const int*   mask = (const int*)  d_in[3];
    const float* Wq   = (const float*)d_in[4];
    const float* Wk   = (const float*)d_in[5];
    const float* Wv   = (const float*)d_in[6];
    const float* Wo   = (const float*)d_in[7];
    const float* bo   = (const float*)d_in[8];

    float* out      = (float*)d_out;
    float* ctx_out  = out;                             // [B,S,DM]
    float* attn_out = out + (size_t)B_ * S_ * DM_;     // [B,H,S,S]

    void *pQ, *pK, *pV, *pC;
    cudaGetSymbolAddress(&pQ, g_Qh);
    cudaGetSymbolAddress(&pK, g_Kh);
    cudaGetSymbolAddress(&pV, g_Vh);
    cudaGetSymbolAddress(&pC, g_Ctx);

    const int smemAttn = SM_WORDS * 4;   // 109056
    cudaFuncSetAttribute(attn_mma, cudaFuncAttributeMaxDynamicSharedMemorySize, smemAttn);

    // QKV projections in ONE launch (1536 proj blocks, 3 GEMMs by bid>>9)
    // + 2048 mask-pack aux blocks filling the wave tail.
    proj_fused<<<1536 + 2048, 256>>>(q, Wq, (float*)pQ,
                                     k, Wk, (float*)pK,
                                     v, Wv, (float*)pV,
                                     nullptr, 1, 1536, mask);

    attn_mma<<<dim3(S_/128, B_*H_), 512, smemAttn>>>(attn_out);

    // Output projection only — attention is written normalized.
    proj_fused<<<512, 256>>>((const float*)pC, Wo, ctx_out,
                             nullptr, nullptr, nullptr,
                             nullptr, nullptr, nullptr,
                             bo, 0, 512, nullptr);
}

// round 17
// speedup vs baseline: 2.0256x; 1.1085x over previous
#include <cuda_runtime.h>
#include <cuda_fp16.h>

#define B_  4
#define S_  2048
#define DM_ 1024
#define H_  16
#define DK_ 64
#define M_  (B_*S_)   // 8192 rows

// Scratch (allocation-free rule: __device__ globals)
__device__ __half g_q16[(size_t)M_*DM_];        // fp16 copies of inputs
__device__ __half g_k16[(size_t)M_*DM_];
__device__ __half g_v16[(size_t)M_*DM_];
__device__ __half g_Wq16[(size_t)DM_*DM_];
__device__ __half g_Wk16[(size_t)DM_*DM_];
__device__ __half g_Wv16[(size_t)DM_*DM_];
__device__ __half g_Wo16[(size_t)DM_*DM_];
__device__ __half g_Qh[(size_t)B_*H_*S_*DK_];   // fp16, pre-scaled by 1/8
__device__ __half g_Kh[(size_t)B_*H_*S_*DK_];   // fp16
__device__ __half g_Vh[(size_t)B_*H_*S_*DK_];   // fp16
__device__ __half g_Ctx16[(size_t)M_*DM_];      // fp16 context
__device__ unsigned g_mbits[(size_t)B_*S_*(S_/32)];   // packed mask bits

// ---------------------------------------------------------------------------
// helpers
// ---------------------------------------------------------------------------
__device__ __forceinline__ unsigned pk_h2(float lo, float hi) {
    unsigned u;
    asm("cvt.rn.f16x2.f32 %0, %1, %2;" : "=r"(u) : "f"(hi), "f"(lo));
    return u;
}
__device__ __forceinline__ void mma_f16(float c[4],
                                        unsigned a0, unsigned a1, unsigned a2, unsigned a3,
                                        unsigned b0, unsigned b1) {
    asm("mma.sync.aligned.m16n8k16.row.col.f32.f16.f16.f32 "
        "{%0,%1,%2,%3},{%4,%5,%6,%7},{%8,%9},{%0,%1,%2,%3};"
        : "+f"(c[0]), "+f"(c[1]), "+f"(c[2]), "+f"(c[3])
        : "r"(a0), "r"(a1), "r"(a2), "r"(a3), "r"(b0), "r"(b1));
}
__device__ __forceinline__ unsigned sm_u32(const void* p) {
    return (unsigned)__cvta_generic_to_shared(p);
}
__device__ __forceinline__ void ldsm4(unsigned r[4], unsigned addr) {
    asm volatile("ldmatrix.sync.aligned.m8n8.x4.shared.b16 {%0,%1,%2,%3}, [%4];"
        : "=r"(r[0]), "=r"(r[1]), "=r"(r[2]), "=r"(r[3]) : "r"(addr));
}
__device__ __forceinline__ void ldsm4t(unsigned r[4], unsigned addr) {
    asm volatile("ldmatrix.sync.aligned.m8n8.x4.trans.shared.b16 {%0,%1,%2,%3}, [%4];"
        : "=r"(r[0]), "=r"(r[1]), "=r"(r[2]), "=r"(r[3]) : "r"(addr));
}
__device__ __forceinline__ void cp16(unsigned dst, const void* src) {
    asm volatile("cp.async.cg.shared.global [%0], [%1], 16;" :: "r"(dst), "l"(src));
}
__device__ __forceinline__ void cp_commit() {
    asm volatile("cp.async.commit_group;");
}
__device__ __forceinline__ void cp_wait0() {
    asm volatile("cp.async.wait_group 0;" ::: "memory");
}

// ---------------------------------------------------------------------------
// Prep: convert q,k,v,Wq,Wk,Wv,Wo to fp16 (blocks 0..1791) + pack mask bits
// (blocks 1792..3839). Pure memory kernel.
// ---------------------------------------------------------------------------
__global__ __launch_bounds__(256) void prep(const float* __restrict__ q,
                                            const float* __restrict__ k,
                                            const float* __restrict__ v,
                                            const float* __restrict__ Wq,
                                            const float* __restrict__ Wk,
                                            const float* __restrict__ Wv,
                                            const float* __restrict__ Wo,
                                            const int* __restrict__ mask)
{
    const int bid = blockIdx.x, tid = threadIdx.x;
    if (bid < 1792) {
        const float* src;
        __half* dst;
        size_t off;
        if      (bid < 512)  { src = q;  dst = g_q16;  off = (size_t)bid * 16384; }
        else if (bid < 1024) { src = k;  dst = g_k16;  off = (size_t)(bid-512) * 16384; }
        else if (bid < 1536) { src = v;  dst = g_v16;  off = (size_t)(bid-1024) * 16384; }
        else if (bid < 1600) { src = Wq; dst = g_Wq16; off = (size_t)(bid-1536) * 16384; }
        else if (bid < 1664) { src = Wk; dst = g_Wk16; off = (size_t)(bid-1600) * 16384; }
        else if (bid < 1728) { src = Wv; dst = g_Wv16; off = (size_t)(bid-1664) * 16384; }
        else                 { src = Wo; dst = g_Wo16; off = (size_t)(bid-1728) * 16384; }
        #pragma unroll 4
        for (int j = 0; j < 16; j++) {
            size_t idx = off + (size_t)j * 1024 + tid * 4;
            float4 f = *(const float4*)&src[idx];
            *(uint2*)&dst[idx] = make_uint2(pk_h2(f.x, f.y), pk_h2(f.z, f.w));
        }
    } else {
        const int aux = bid - 1792;
        const int lane = tid & 31, w = tid >> 5;
        size_t base = (size_t)aux * 256 + (size_t)w * 32;
        #pragma unroll 4
        for (int i = 0; i < 32; i++) {
            int m = mask[(base + i) * 32 + lane];
            unsigned bits = __ballot_sync(0xffffffffu, m != 0);
            if (lane == 0) g_mbits[base + i] = bits;
        }
    }
}

// ---------------------------------------------------------------------------
// Projection GEMM, fp16 in / fp16 or fp32 out, cp.async feed, double-buffered.
// Up to 3 GEMMs per launch by bid>>9. Tile 128x128, BK=32, 8 warps 2(m)x4(n).
// Per iter: 4 cp16/thread (X+W tiles) + 12 ldsm4 + 32 mma_f16 per warp.
// ---------------------------------------------------------------------------
#define XSTRH 20   // words per 32-half row (16 data + 4 pad)
#define PBUFW 2560 // words per tile buffer (128 * 20)
__global__ __launch_bounds__(256, 2) void proj_fused(
    const __half* __restrict__ X0, const __half* __restrict__ W0, void* __restrict__ Y0,
    const __half* __restrict__ X1, const __half* __restrict__ W1, void* __restrict__ Y1,
    const __half* __restrict__ X2, const __half* __restrict__ W2, void* __restrict__ Y2,
    const float* __restrict__ bias,
    int headsMode)
{
    __shared__ unsigned psm[4 * PBUFW];  // Xbuf0 | Xbuf1 | Wbuf0 | Wbuf1
    const int bid = blockIdx.x;
    const int which = bid >> 9;        // which GEMM (0..2)
    const int sub = bid & 511;
    const __half* X = (which == 0) ? X0 : (which == 1) ? X1 : X2;
    const __half* W = (which == 0) ? W0 : (which == 1) ? W1 : W2;
    void*         Y = (which == 0) ? Y0 : (which == 1) ? Y1 : Y2;

    const int tid = threadIdx.x;
    const int lane = tid & 31, wid = tid >> 5;
    const int wm = wid >> 2, wn = wid & 3;
    const int gr = lane >> 2, tg = lane & 3;
    const int m0 = (sub & 63) * 128, n0 = (sub >> 6) * 128;

    const unsigned abase = sm_u32(psm + (wm*64 + (lane & 15))*XSTRH + ((lane >> 4) & 1)*4);
    const unsigned bbase = sm_u32(psm + 2*PBUFW
                                  + (wn*32 + (lane & 7) + ((lane >> 3) & 1)*8)*XSTRH
                                  + ((lane >> 4) & 1)*4);

    const int lr = tid >> 1;          // 0..127 (row)
    const int ch = (tid & 1) * 16;    // half-chunk within row (halves)
    const unsigned xsts = sm_u32(psm + lr*XSTRH + (ch >> 1));
    const unsigned wsts = sm_u32(psm + 2*PBUFW + lr*XSTRH + (ch >> 1));

    float c[4][4][4];
    #pragma unroll
    for (int mi = 0; mi < 4; mi++)
        #pragma unroll
        for (int ni = 0; ni < 4; ni++)
            #pragma unroll
            for (int r = 0; r < 4; r++) c[mi][ni][r] = 0.f;

    const __half* Xp = X + (size_t)(m0 + lr) * DM_ + ch;
    const __half* Wp = W + (size_t)(n0 + lr) * DM_ + ch;

    { // prologue: iter 0 -> buffer 0
        cp16(xsts,       Xp);
        cp16(xsts + 16u, Xp + 8);
        cp16(wsts,       Wp);
        cp16(wsts + 16u, Wp + 8);
        cp_commit();
        cp_wait0();
    }

    #pragma unroll 1
    for (int it = 0; it < 32; it++) {
        __syncthreads();               // all warps done with mma on the other buffer
        if (it + 1 < 32) {
            const unsigned boff = ((it + 1) & 1) * (PBUFW * 4u);
            const __half* Xn = Xp + (it + 1) * 32;
            const __half* Wn = Wp + (it + 1) * 32;
            cp16(xsts + boff,       Xn);
            cp16(xsts + boff + 16u, Xn + 8);
            cp16(wsts + boff,       Wn);
            cp16(wsts + boff + 16u, Wn + 8);
            cp_commit();
        }

        const unsigned bufOff = (it & 1) * (PBUFW * 4u);
        #pragma unroll
        for (int kc = 0; kc < 2; kc++) {           // two k16 chunks
            unsigned a[4][4], bbf[4][2];
            #pragma unroll
            for (int mi = 0; mi < 4; mi++)
                ldsm4(a[mi], abase + bufOff + (unsigned)(mi*16*XSTRH + kc*8) * 4u);
            #pragma unroll
            for (int np = 0; np < 2; np++) {
                unsigned t[4];
                ldsm4(t, bbase + bufOff + (unsigned)(np*16*XSTRH + kc*8) * 4u);
                bbf[2*np][0]   = t[0]; bbf[2*np][1]   = t[2];
                bbf[2*np+1][0] = t[1]; bbf[2*np+1][1] = t[3];
            }
            #pragma unroll
            for (int mi = 0; mi < 4; mi++)
                #pragma unroll
                for (int ni = 0; ni < 4; ni++)
                    mma_f16(c[mi][ni], a[mi][0], a[mi][1], a[mi][2], a[mi][3],
                            bbf[ni][0], bbf[ni][1]);
        }
        cp_wait0();                    // next tile landed (overlapped with mma)
    }

    if (headsMode) {
        const float s = (which == 0) ? 0.125f : 1.0f;
        __half* Yh = (__half*)Y;
        #pragma unroll
        for (int mi = 0; mi < 4; mi++) {
            int m = m0 + wm*64 + mi*16 + gr;
            int b = m >> 11, sq = m & (S_ - 1);
            #pragma unroll
            for (int ni = 0; ni < 4; ni++) {
                int n = n0 + wn*32 + ni*8 + 2*tg;
                int h = n >> 6, dk = n & 63;
                size_t base = (((size_t)(b*H_ + h) * S_) + sq) * DK_ + dk;
                *(unsigned*)&Yh[base]          = pk_h2(c[mi][ni][0]*s, c[mi][ni][1]*s);
                *(unsigned*)&Yh[base + 8*DK_]  = pk_h2(c[mi][ni][2]*s, c[mi][ni][3]*s);
            }
        }
    } else {
        float* Yf = (float*)Y;
        #pragma unroll
        for (int mi = 0; mi < 4; mi++) {
            int m = m0 + wm*64 + mi*16 + gr;
            #pragma unroll
            for (int ni = 0; ni < 4; ni++) {
                int n = n0 + wn*32 + ni*8 + 2*tg;
                float b0 = bias[n], b1 = bias[n+1];
                *(float2*)&Yf[(size_t)m * DM_ + n] =
                    make_float2(c[mi][ni][0] + b0, c[mi][ni][1] + b1);
                *(float2*)&Yf[(size_t)(m+8) * DM_ + n] =
                    make_float2(c[mi][ni][2] + b0, c[mi][ni][3] + b1);
            }
        }
    }
}

// ---------------------------------------------------------------------------
// Fused attention (unchanged from R16 except fp16 context output).
// smem words: Qs(h) 4608 | Ks(h) 2x4608 | Vs(h) 4608 | Ps(h) 8704 | rowSum 128
// ---------------------------------------------------------------------------
#define QSTRH 36      // words per 64-half row (32 + 4 pad)
#define VSTRH 36
#define PSTRH 68      // words per 128-half row (64 + 4 pad)
#define OFF_KS 4608
#define OFF_VS 13824
#define OFF_PS 18432
#define OFF_RS 27136
#define SM_WORDS 27264
#define KBYTES (4608u * 4u)

__global__ __launch_bounds__(512) void attn_mma(float* __restrict__ attn)
{
    extern __shared__ unsigned smu[];
    unsigned* Qs = smu;            // fp16 [q][d], stride 36 words
    unsigned* Ks = smu + OFF_KS;   // fp16, two buffers of 4608 words
    unsigned* Vs = smu + OFF_VS;   // fp16 [key][d], stride 36 words
    unsigned* Ps = smu + OFF_PS;   // fp16 [q][k], stride 68 words
    float* rowSum = (float*)(smu + OFF_RS);   // later holds 1/l

    const int tid = threadIdx.x;
    const int lane = tid & 31, wid = tid >> 5;
    const int wm = wid >> 2, wn = wid & 3;       // score map: 32q x 32k
    const int wm2 = wid & 3, wn2 = wid >> 2;     // PV map:    32q x 16d
    const int gr = lane >> 2, tg = lane & 3;
    const int qt = blockIdx.x, bh = blockIdx.y;
    const int b = bh >> 4, h = bh & 15;

    const unsigned qbase = sm_u32(Qs + (wm*32 + (lane & 15))*QSTRH + ((lane >> 4) & 1)*4);
    const unsigned kbase = sm_u32(Ks + (wn*32 + (lane & 7) + ((lane >> 3) & 1)*8)*QSTRH
                                     + ((lane >> 4) & 1)*4);
    const unsigned pbase = sm_u32(Ps + (wm2*32 + (lane & 15))*PSTRH + ((lane >> 4) & 1)*4);
    const unsigned vbase = sm_u32((char*)Vs
        + (size_t)(((lane >> 3) & 1) * 8 + (lane & 7)) * (VSTRH*4)
        + (size_t)(wn2*16 + (lane >> 4) * 8) * 2);

    const __half* Qb = g_Qh + ((size_t)bh * S_ + qt*128) * DK_;
    const __half* Kb = g_Kh + (size_t)bh * S_ * DK_;
    const __half* Vb = g_Vh + (size_t)bh * S_ * DK_;
    const unsigned* mbp = g_mbits + ((size_t)b * S_ + qt*128) * (S_/32);
    float* ab = attn + (size_t)bh * S_ * S_ + (size_t)qt * 128 * S_;

    if (tid < 128) rowSum[tid] = 0.f;

    const int lr = tid >> 2;            // 0..127
    const int segh = (tid & 3) * 16;    // d quarter in halves
    const unsigned qsts = sm_u32(Qs + lr*QSTRH + (segh >> 1));
    const unsigned ksts = sm_u32(Ks + lr*QSTRH + (segh >> 1));
    const unsigned vsts = sm_u32(Vs + lr*VSTRH + (segh >> 1));

    { // prologue: Q tile + K[0] via cp.async (fp16: 2x16B each)
        const __half* qp = Qb + (size_t)lr * DK_ + segh;
        const __half* kp = Kb + (size_t)lr * DK_ + segh;
        cp16(qsts,       qp);
        cp16(qsts + 16u, qp + 8);
        cp16(ksts,       kp);
        cp16(ksts + 16u, kp + 8);
        cp_commit();
        cp_wait0();
    }

    float lacc[4];
    #pragma unroll
    for (int i = 0; i < 4; i++) lacc[i] = 0.f;

    // ================= PASS 1: row sums only =================
    for (int kt = 0; kt < 16; kt++) {
        __syncthreads();
        if (kt + 1 < 16) {
            const __half* kp = Kb + (size_t)((kt+1)*128 + lr) * DK_ + segh;
            const unsigned kdst = ksts + ((kt+1) & 1) * KBYTES;
            cp16(kdst,       kp);
            cp16(kdst + 16u, kp + 8);
            cp_commit();
        }
        unsigned mw[2][2];
        #pragma unroll
        for (int mi = 0; mi < 2; mi++) {
            const int r0 = wm*32 + mi*16 + gr;
            mw[mi][0] = mbp[(size_t)r0      * (S_/32) + kt*4 + wn];
            mw[mi][1] = mbp[(size_t)(r0+8)  * (S_/32) + kt*4 + wn];
        }

        const unsigned kb = kbase + (kt & 1) * KBYTES;
        float sc[2][4][4];
        #pragma unroll
        for (int mi = 0; mi < 2; mi++)
            #pragma unroll
            for (int ni = 0; ni < 4; ni++)
                #pragma unroll
                for (int r = 0; r < 4; r++) sc[mi][ni][r] = 0.f;

        #pragma unroll
        for (int kc = 0; kc < 4; kc++) {          // k16 per step
            unsigned a[2][4], bbf[4][2];
            ldsm4(a[0], qbase + (unsigned)(kc*8) * 4u);
            ldsm4(a[1], qbase + (unsigned)(16*QSTRH + kc*8) * 4u);
            #pragma unroll
            for (int np = 0; np < 2; np++) {
                unsigned t[4];
                ldsm4(t, kb + (unsigned)(np*16*QSTRH + kc*8) * 4u);
                bbf[2*np][0]   = t[0]; bbf[2*np][1]   = t[2];
                bbf[2*np+1][0] = t[1]; bbf[2*np+1][1] = t[3];
            }
            #pragma unroll
            for (int mi = 0; mi < 2; mi++)
                #pragma unroll
                for (int ni = 0; ni < 4; ni++)
                    mma_f16(sc[mi][ni], a[mi][0], a[mi][1], a[mi][2], a[mi][3],
                            bbf[ni][0], bbf[ni][1]);
        }

        #pragma unroll
        for (int mi = 0; mi < 2; mi++) {
            #pragma unroll
            for (int ni = 0; ni < 4; ni++) {
                const int bit = ni*8 + 2*tg;
                float p00 = (mw[mi][0] >> bit     & 1u) ? __expf(sc[mi][ni][0]) : 0.f;
                float p01 = (mw[mi][0] >> (bit+1) & 1u) ? __expf(sc[mi][ni][1]) : 0.f;
                float p10 = (mw[mi][1] >> bit     & 1u) ? __expf(sc[mi][ni][2]) : 0.f;
                float p11 = (mw[mi][1] >> (bit+1) & 1u) ? __expf(sc[mi][ni][3]) : 0.f;
                lacc[mi*2]   += p00 + p01;
                lacc[mi*2+1] += p10 + p11;
            }
        }
        cp_wait0();        // K[kt+1] landed, overlapped with scores+exp
    }

    // ---- reduce row sums; rowSum becomes 1/l ----
    #pragma unroll
    for (int i = 0; i < 4; i++) {
        float v = lacc[i];
        v += __shfl_xor_sync(0xffffffffu, v, 1);
        v += __shfl_xor_sync(0xffffffffu, v, 2);
        lacc[i] = v;
    }
    if (tg == 0) {
        #pragma unroll
        for (int mi = 0; mi < 2; mi++) {
            atomicAdd(&rowSum[wm*32 + mi*16 + gr],     lacc[mi*2]);
            atomicAdd(&rowSum[wm*32 + mi*16 + gr + 8], lacc[mi*2+1]);
        }
    }
    __syncthreads();
    if (tid < 128) rowSum[tid] = 1.0f / rowSum[tid];
    __syncthreads();

    float inv0[2], inv1[2];
    #pragma unroll
    for (int mi = 0; mi < 2; mi++) {
        inv0[mi] = rowSum[wm*32 + mi*16 + gr];
        inv1[mi] = rowSum[wm*32 + mi*16 + gr + 8];
    }

    { // pass-2 prologue: K[0] into buffer 0
        const __half* kp = Kb + (size_t)lr * DK_ + segh;
        cp16(ksts,       kp);
        cp16(ksts + 16u, kp + 8);
        cp_commit();
        cp_wait0();
    }

    float cacc[2][2][4];
    #pragma unroll
    for (int mi = 0; mi < 2; mi++)
        #pragma unroll
        for (int f = 0; f < 2; f++)
            #pragma unroll
            for (int r = 0; r < 4; r++) cacc[mi][f][r] = 0.f;

    // ================= PASS 2: normalized probs + PV =================
    for (int kt = 0; kt < 16; kt++) {
        __syncthreads();   // prev PV done with Vs/Ps; K[kt] visible
        {
            const __half* vp = Vb + (size_t)(kt*128 + lr) * DK_ + segh;
            cp16(vsts,       vp);
            cp16(vsts + 16u, vp + 8);
            if (kt + 1 < 16) {
                const __half* kp = Kb + (size_t)((kt+1)*128 + lr) * DK_ + segh;
                const unsigned kdst = ksts + ((kt+1) & 1) * KBYTES;
                cp16(kdst,       kp);
                cp16(kdst + 16u, kp + 8);
            }
            cp_commit();
        }
        unsigned mw[2][2];
        #pragma unroll
        for (int mi = 0; mi < 2; mi++) {
            const int r0 = wm*32 + mi*16 + gr;
            mw[mi][0] = mbp[(size_t)r0      * (S_/32) + kt*4 + wn];
            mw[mi][1] = mbp[(size_t)(r0+8)  * (S_/32) + kt*4 + wn];
        }

        const unsigned kb = kbase + (kt & 1) * KBYTES;
        float sc[2][4][4];
        #pragma unroll
        for (int mi = 0; mi < 2; mi++)
            #pragma unroll
            for (int ni = 0; ni < 4; ni++)
                #pragma unroll
                for (int r = 0; r < 4; r++) sc[mi][ni][r] = 0.f;

        #pragma unroll
        for (int kc = 0; kc < 4; kc++) {
            unsigned a[2][4], bbf[4][2];
            ldsm4(a[0], qbase + (unsigned)(kc*8) * 4u);
            ldsm4(a[1], qbase + (unsigned)(16*QSTRH + kc*8) * 4u);
            #pragma unroll
            for (int np = 0; np < 2; np++) {
                unsigned t[4];
                ldsm4(t, kb + (unsigned)(np*16*QSTRH + kc*8) * 4u);
                bbf[2*np][0]   = t[0]; bbf[2*np][1]   = t[2];
                bbf[2*np+1][0] = t[1]; bbf[2*np+1][1] = t[3];
            }
            #pragma unroll
            for (int mi = 0; mi < 2; mi++)
                #pragma unroll
                for (int ni = 0; ni < 4; ni++)
                    mma_f16(sc[mi][ni], a[mi][0], a[mi][1], a[mi][2], a[mi][3],
                            bbf[ni][0], bbf[ni][1]);
        }

        // mask + exp, normalized; write final probs (fp32) + Ps (fp16)
        #pragma unroll
        for (int mi = 0; mi < 2; mi++) {
            const int r0 = wm*32 + mi*16 + gr;
            #pragma unroll
            for (int ni = 0; ni < 4; ni++) {
                const int ck = wn*32 + ni*8 + 2*tg;
                const int bit = ni*8 + 2*tg;
                const size_t gcol = (size_t)kt*128 + ck;
                float p00 = (mw[mi][0] >> bit     & 1u) ? __expf(sc[mi][ni][0]) * inv0[mi] : 0.f;
                float p01 = (mw[mi][0] >> (bit+1) & 1u) ? __expf(sc[mi][ni][1]) * inv0[mi] : 0.f;
                float p10 = (mw[mi][1] >> bit     & 1u) ? __expf(sc[mi][ni][2]) * inv1[mi] : 0.f;
                float p11 = (mw[mi][1] >> (bit+1) & 1u) ? __expf(sc[mi][ni][3]) * inv1[mi] : 0.f;
                *(float2*)&ab[(size_t)r0     * S_ + gcol] = make_float2(p00, p01);
                *(float2*)&ab[(size_t)(r0+8) * S_ + gcol] = make_float2(p10, p11);
                Ps[r0    *PSTRH + (ck >> 1)] = pk_h2(p00, p01);
                Ps[(r0+8)*PSTRH + (ck >> 1)] = pk_h2(p10, p11);
            }
        }
        cp_wait0();        // V[kt] (and K[kt+1]) landed
        __syncthreads();   // P + V visible to all threads

        // ---- PV (fp16 m16n8k16): warp 32q x 16d, 8 chunks of 16 keys ----
        #pragma unroll
        for (int kc = 0; kc < 8; kc++) {
            unsigned a2[2][4];
            ldsm4(a2[0], pbase + (unsigned)(kc*8) * 4u);
            ldsm4(a2[1], pbase + (unsigned)(16*PSTRH + kc*8) * 4u);
            unsigned vbf[4];
            ldsm4t(vbf, vbase + (unsigned)(kc*16*VSTRH) * 4u);
            #pragma unroll
            for (int mi = 0; mi < 2; mi++) {
                mma_f16(cacc[mi][0], a2[mi][0], a2[mi][1], a2[mi][2], a2[mi][3],
                        vbf[0], vbf[1]);
                mma_f16(cacc[mi][1], a2[mi][0], a2[mi][1], a2[mi][2], a2[mi][3],
                        vbf[2], vbf[3]);
            }
        }
    }

    // ---- context write (fp16, already normalized), [b][s][h*64+d] ----
    #pragma unroll
    for (int mi = 0; mi < 2; mi++) {
        const int r0 = wm2*32 + mi*16 + gr;
        #pragma unroll
        for (int f = 0; f < 2; f++) {
            const int d = wn2*16 + f*8 + 2*tg;
            size_t d0 = ((size_t)(b*S_ + qt*128 + r0    )) * DM_ + h*DK_ + d;
            size_t d1 = ((size_t)(b*S_ + qt*128 + r0 + 8)) * DM_ + h*DK_ + d;
            *(unsigned*)&g_Ctx16[d0] = pk_h2(cacc[mi][f][0], cacc[mi][f][1]);
            *(unsigned*)&g_Ctx16[d1] = pk_h2(cacc[mi][f][2], cacc[mi][f][3]);
        }
    }
}

// ---------------------------------------------------------------------------
extern "C" void kernel_launch(void* const* d_in, const int* in_sizes, int n_in,
                              void* d_out, int out_size)
{
    const float* q    = (const float*)d_in[0];
    const float* k    = (const float*)d_in[1];
    const float* v    = (const float*)d_in[2];
    const int*   mask = (const int*)  d_in[3];
    const float* Wq   = (const float*)d_in[4];
    const float* Wk   = (const float*)d_in[5];
    const float* Wv   = (const float*)d_in[6];
    const float* Wo   = (const float*)d_in[7];
    const float* bo   = (const float*)d_in[8];

    float* out      = (float*)d_out;
    float* ctx_out  = out;                             // [B,S,DM]
    float* attn_out = out + (size_t)B_ * S_ * DM_;     // [B,H,S,S]

    void *pq16, *pk16, *pv16, *pWq, *pWk, *pWv, *pWo, *pQ, *pK, *pV, *pC;
    cudaGetSymbolAddress(&pq16, g_q16);
    cudaGetSymbolAddress(&pk16, g_k16);
    cudaGetSymbolAddress(&pv16, g_v16);
    cudaGetSymbolAddress(&pWq, g_Wq16);
    cudaGetSymbolAddress(&pWk, g_Wk16);
    cudaGetSymbolAddress(&pWv, g_Wv16);
    cudaGetSymbolAddress(&pWo, g_Wo16);
    cudaGetSymbolAddress(&pQ, g_Qh);
    cudaGetSymbolAddress(&pK, g_Kh);
    cudaGetSymbolAddress(&pV, g_Vh);
    cudaGetSymbolAddress(&pC, g_Ctx16);

    const int smemAttn = SM_WORDS * 4;   // 109056
    cudaFuncSetAttribute(attn_mma, cudaFuncAttributeMaxDynamicSharedMemorySize, smemAttn);

    // 1) convert inputs + weights to fp16, pack mask bits
    prep<<<3840, 256>>>(q, k, v, Wq, Wk, Wv, Wo, mask);

    // 2) QKV projections in one launch (3 GEMMs by bid>>9)
    proj_fused<<<1536, 256>>>((const __half*)pq16, (const __half*)pWq, pQ,
                              (const __half*)pk16, (const __half*)pWk, pK,
                              (const __half*)pv16, (const __half*)pWv, pV,
                              nullptr, 1);

    // 3) attention (fp16 context out, normalized attn out)
    attn_mma<<<dim3(S_/128, B_*H_), 512, smemAttn>>>(attn_out);

    // 4) output projection (fp16 ctx @ fp16 Wo -> fp32 + bias)
    proj_fused<<<512, 256>>>((const __half*)pC, (const __half*)pWo, ctx_out,
                             nullptr, nullptr, nullptr,
                             nullptr, nullptr, nullptr,
                             bo, 0);
}